// round 13
// baseline (speedup 1.0000x reference)
#include <cuda_runtime.h>
#include <cuda_fp16.h>
#include <math.h>
#include <stdint.h>
#include <string.h>

// Problem constants
#define BB   2
#define SS   2048
#define DD   1024
#define HH   16
#define DH   64
#define FF   4096
#define NTOK (BB*SS)          // 4096 rows
#define D3   (3*DD)           // 3072

// ---------------------------------------------------------------------------
// Scratch (static device globals)
// ---------------------------------------------------------------------------
__device__ float  g_proj[NTOK * DD];
__device__ float  g_hbuf[NTOK * DD];
__device__ float  g_m2  [NTOK * DD];
__device__ __half g_qkvh [NTOK * D3];
__device__ __half g_xh   [NTOK * DD];
__device__ __half g_wqkvh[D3 * DD];
__device__ __half g_woh  [DD * DD];
__device__ __half g_w1h  [2 * FF * DD];
__device__ __half g_w2h  [DD * FF];
__device__ __half g_attnh[NTOK * DD];
__device__ __half g_hh   [NTOK * DD];
__device__ __half g_mh   [NTOK * FF];
__device__ __half g_qh   [NTOK * DD];
__device__ __half g_kh   [NTOK * DD];
__device__ __half g_vth  [BB * HH * DH * SS];

// ---------------------------------------------------------------------------
// helpers
// ---------------------------------------------------------------------------
__device__ __forceinline__ uint32_t h2_as_u32(__half2 h) {
    uint32_t u; memcpy(&u, &h, 4); return u;
}

__device__ __forceinline__ void mma_f16(
    float& d0, float& d1, float& d2, float& d3,
    uint32_t a0, uint32_t a1, uint32_t a2, uint32_t a3,
    uint32_t b0, uint32_t b1)
{
    asm volatile(
        "mma.sync.aligned.m16n8k16.row.col.f32.f16.f16.f32 "
        "{%0,%1,%2,%3}, {%4,%5,%6,%7}, {%8,%9}, {%0,%1,%2,%3};"
        : "+f"(d0), "+f"(d1), "+f"(d2), "+f"(d3)
        : "r"(a0), "r"(a1), "r"(a2), "r"(a3), "r"(b0), "r"(b1));
}

__device__ __forceinline__ void ldsm_x4(
    uint32_t& r0, uint32_t& r1, uint32_t& r2, uint32_t& r3, uint32_t addr)
{
    asm volatile(
        "ldmatrix.sync.aligned.m8n8.x4.shared.b16 {%0,%1,%2,%3}, [%4];"
        : "=r"(r0), "=r"(r1), "=r"(r2), "=r"(r3) : "r"(addr));
}

__device__ __forceinline__ uint32_t smem_u32(const void* p) {
    uint32_t a;
    asm("{ .reg .u64 t; cvta.to.shared.u64 t, %1; cvt.u32.u64 %0, t; }"
        : "=r"(a) : "l"(p));
    return a;
}

__device__ __forceinline__ void cp_async16(uint32_t s, const void* g) {
    asm volatile("cp.async.cg.shared.global [%0], [%1], 16;\n"
                 :: "r"(s), "l"(g));
}
__device__ __forceinline__ void cp_commit() {
    asm volatile("cp.async.commit_group;\n");
}
template<int N> __device__ __forceinline__ void cp_wait() {
    asm volatile("cp.async.wait_group %0;\n" :: "n"(N));
}

__device__ __forceinline__ void store2(float* C, size_t idx, float a, float b) {
    *(float2*)&C[idx] = make_float2(a, b);
}
__device__ __forceinline__ void store2(__half* C, size_t idx, float a, float b) {
    *(__half2*)&C[idx] = __floats2half2_rn(a, b);
}

// ---------------------------------------------------------------------------
// Merged fp32 -> fp16 conversion for all five GEMM inputs (one launch)
// ---------------------------------------------------------------------------
#define CP_N0 (NTOK * DD / 4)                 // x      : 1048576
#define CP_N1 (CP_N0 + D3 * DD / 4)           // +wqkv  : 786432
#define CP_N2 (CP_N1 + DD * DD / 4)           // +wo    : 262144
#define CP_N3 (CP_N2 + 2 * FF * DD / 4)       // +w1    : 2097152
#define CP_N4 (CP_N3 + DD * FF / 4)           // +w2    : 1048576

__global__ void __launch_bounds__(256) h_copy_all(
    const float* __restrict__ x, const float* __restrict__ wqkv,
    const float* __restrict__ wo, const float* __restrict__ w1,
    const float* __restrict__ w2,
    __half* __restrict__ xh, __half* __restrict__ wqkvh,
    __half* __restrict__ woh, __half* __restrict__ w1h,
    __half* __restrict__ w2h)
{
    int i = blockIdx.x * blockDim.x + threadIdx.x;
    if (i >= CP_N4) return;
    const float* s; __half* d; int off;
    if      (i < CP_N0) { s = x;    d = xh;    off = i; }
    else if (i < CP_N1) { s = wqkv; d = wqkvh; off = i - CP_N0; }
    else if (i < CP_N2) { s = wo;   d = woh;   off = i - CP_N1; }
    else if (i < CP_N3) { s = w1;   d = w1h;   off = i - CP_N2; }
    else                { s = w2;   d = w2h;   off = i - CP_N3; }
    float4 v = ((const float4*)s)[off];
    ((__half2*)d)[2 * off]     = __floats2half2_rn(v.x, v.y);
    ((__half2*)d)[2 * off + 1] = __floats2half2_rn(v.z, v.w);
}

// ---------------------------------------------------------------------------
// GEMM tile parameters: CTA 128x128, BK=64, 3-stage cp.async, 8 warps.
// Row stride 72 halves (144B): ldmatrix 16B-unit index = 9*row mod 8 = row -> CF.
// ---------------------------------------------------------------------------
#define HSTR    72
#define STAGE_H (2 * 128 * HSTR)           // 18432 halves
#define GH_SMEM (3 * STAGE_H * 2)          // 110592 B

// ---------------------------------------------------------------------------
// FP16 tensor-core GEMM: C = A @ W^T + bias
// ---------------------------------------------------------------------------
template<typename OutT>
__global__ void __launch_bounds__(256, 2) gemm_f16_nt_bias(
    const __half* __restrict__ A, const __half* __restrict__ W,
    const float* __restrict__ bias, OutT* __restrict__ C,
    int M, int N, int K)
{
    extern __shared__ __align__(16) char smc[];
    __half* smh = (__half*)smc;

    const int tid  = threadIdx.x;
    const int m0   = blockIdx.y * 128;
    const int n0   = blockIdx.x * 128;
    const int warp = tid >> 5;
    const int lane = tid & 31;
    const int g    = lane >> 2;
    const int t    = lane & 3;
    const int wm   = (warp >> 2) * 64;
    const int wn   = (warp & 3) * 32;

    const int lrow = tid >> 1;             // 0..127
    const int lc   = (tid & 1) * 32;       // 0 or 32 halves
    const __half* Ag = A + (size_t)(m0 + lrow) * K + lc;
    const __half* Wg = W + (size_t)(n0 + lrow) * K + lc;
    const uint32_t smb = smem_u32(smh);

    const int NK = K >> 6;                 // BK = 64

    auto issue = [&](int kt) {
        const int buf = kt % 3;
        uint32_t dA = smb + (uint32_t)(buf * STAGE_H + lrow * HSTR + lc) * 2;
        uint32_t dB = dA + 128 * HSTR * 2;
        const __half* a = Ag + (size_t)kt * 64;
        const __half* w = Wg + (size_t)kt * 64;
        cp_async16(dA,      a);      cp_async16(dA + 16, a + 8);
        cp_async16(dA + 32, a + 16); cp_async16(dA + 48, a + 24);
        cp_async16(dB,      w);      cp_async16(dB + 16, w + 8);
        cp_async16(dB + 32, w + 16); cp_async16(dB + 48, w + 24);
        cp_commit();
    };

    const uint32_t aRow = (uint32_t)(lane & 15);
    const uint32_t aKh  = (uint32_t)((lane >> 4) << 3);
    const uint32_t bRow = (uint32_t)((lane & 7) + ((lane >> 4) << 3));
    const uint32_t bKh  = (uint32_t)(lane & 8);

    uint32_t af0[4][4], bf0[4][2], af1[4][4], bf1[4][2];

    auto ldfrag = [&](int buf, int ks, uint32_t af[4][4], uint32_t bf[4][2]) {
        const uint32_t aBase = smb + (uint32_t)(buf * STAGE_H) * 2;
        const uint32_t bBase = aBase + 128 * HSTR * 2;
        const uint32_t kh = (uint32_t)(ks * 16);
#pragma unroll
        for (int i = 0; i < 4; i++) {
            uint32_t addr = aBase + (((uint32_t)(wm + i * 16) + aRow) * HSTR + kh + aKh) * 2;
            ldsm_x4(af[i][0], af[i][1], af[i][2], af[i][3], addr);
        }
#pragma unroll
        for (int jp = 0; jp < 2; jp++) {
            uint32_t addr = bBase + (((uint32_t)(wn + jp * 16) + bRow) * HSTR + kh + bKh) * 2;
            ldsm_x4(bf[2 * jp][0], bf[2 * jp][1], bf[2 * jp + 1][0], bf[2 * jp + 1][1], addr);
        }
    };

    float acc[4][4][4];
#pragma unroll
    for (int i = 0; i < 4; i++)
#pragma unroll
        for (int j = 0; j < 4; j++)
#pragma unroll
            for (int r = 0; r < 4; r++) acc[i][j][r] = 0.f;

    auto mma16 = [&](uint32_t af[4][4], uint32_t bf[4][2]) {
#pragma unroll
        for (int j = 0; j < 4; j++)
#pragma unroll
            for (int i = 0; i < 4; i++)
                mma_f16(acc[i][j][0], acc[i][j][1], acc[i][j][2], acc[i][j][3],
                        af[i][0], af[i][1], af[i][2], af[i][3],
                        bf[j][0], bf[j][1]);
    };

    issue(0);
    issue(1);
    cp_wait<1>();
    __syncthreads();
    ldfrag(0, 0, af0, bf0);

    for (int kt = 0; kt < NK; kt++) {
        const int buf = kt % 3;
        ldfrag(buf, 1, af1, bf1);
        mma16(af0, bf0);
        const bool more2 = (kt + 2) < NK;
        if (more2) issue(kt + 2);
        ldfrag(buf, 2, af0, bf0);
        mma16(af1, bf1);
        ldfrag(buf, 3, af1, bf1);
        mma16(af0, bf0);
        mma16(af1, bf1);
        if (kt + 1 < NK) {
            if (more2) cp_wait<1>();
            else       cp_wait<0>();
            __syncthreads();
            ldfrag((kt + 1) % 3, 0, af0, bf0);
        }
    }

#pragma unroll
    for (int i = 0; i < 4; i++) {
        const int r0 = m0 + wm + i * 16 + g;
        const int r1 = r0 + 8;
#pragma unroll
        for (int j = 0; j < 4; j++) {
            const int col = n0 + wn + j * 8 + 2 * t;
            float2 bv = *(const float2*)&bias[col];
            store2(C, (size_t)r0 * N + col, acc[i][j][0] + bv.x, acc[i][j][1] + bv.y);
            store2(C, (size_t)r1 * N + col, acc[i][j][2] + bv.x, acc[i][j][3] + bv.y);
        }
    }
}

// ---------------------------------------------------------------------------
// W1 GEMM fused with GELU*gate (BK=64 mainloop; epilogue as R11)
// ---------------------------------------------------------------------------
#define CS_STR   132
#define W1_SMEM  GH_SMEM                   // staging (67584 B) < GH_SMEM

__global__ void __launch_bounds__(256, 2) gemm_w1_gelu(
    const __half* __restrict__ A, const __half* __restrict__ W,
    const float* __restrict__ bias, __half* __restrict__ Mout,
    int M, int K)
{
    extern __shared__ __align__(16) char smc[];
    __half* smh = (__half*)smc;

    const int tid  = threadIdx.x;
    const int m0   = blockIdx.y * 128;
    const int n0m  = blockIdx.x * 64;
    const int warp = tid >> 5;
    const int lane = tid & 31;
    const int g    = lane >> 2;
    const int t    = lane & 3;
    const int wm   = (warp >> 2) * 64;
    const int wn   = (warp & 3) * 32;

    const int lrow = tid >> 1;
    const int lc   = (tid & 1) * 32;
    const int wrow = (lrow < 64) ? (n0m + lrow) : (FF + n0m + lrow - 64);
    const __half* Ag = A + (size_t)(m0 + lrow) * K + lc;
    const __half* Wg = W + (size_t)wrow * K + lc;
    const uint32_t smb = smem_u32(smh);

    const int NK = K >> 6;

    auto issue = [&](int kt) {
        const int buf = kt % 3;
        uint32_t dA = smb + (uint32_t)(buf * STAGE_H + lrow * HSTR + lc) * 2;
        uint32_t dB = dA + 128 * HSTR * 2;
        const __half* a = Ag + (size_t)kt * 64;
        const __half* w = Wg + (size_t)kt * 64;
        cp_async16(dA,      a);      cp_async16(dA + 16, a + 8);
        cp_async16(dA + 32, a + 16); cp_async16(dA + 48, a + 24);
        cp_async16(dB,      w);      cp_async16(dB + 16, w + 8);
        cp_async16(dB + 32, w + 16); cp_async16(dB + 48, w + 24);
        cp_commit();
    };

    const uint32_t aRow = (uint32_t)(lane & 15);
    const uint32_t aKh  = (uint32_t)((lane >> 4) << 3);
    const uint32_t bRow = (uint32_t)((lane & 7) + ((lane >> 4) << 3));
    const uint32_t bKh  = (uint32_t)(lane & 8);

    uint32_t af0[4][4], bf0[4][2], af1[4][4], bf1[4][2];

    auto ldfrag = [&](int buf, int ks, uint32_t af[4][4], uint32_t bf[4][2]) {
        const uint32_t aBase = smb + (uint32_t)(buf * STAGE_H) * 2;
        const uint32_t bBase = aBase + 128 * HSTR * 2;
        const uint32_t kh = (uint32_t)(ks * 16);
#pragma unroll
        for (int i = 0; i < 4; i++) {
            uint32_t addr = aBase + (((uint32_t)(wm + i * 16) + aRow) * HSTR + kh + aKh) * 2;
            ldsm_x4(af[i][0], af[i][1], af[i][2], af[i][3], addr);
        }
#pragma unroll
        for (int jp = 0; jp < 2; jp++) {
            uint32_t addr = bBase + (((uint32_t)(wn + jp * 16) + bRow) * HSTR + kh + bKh) * 2;
            ldsm_x4(bf[2 * jp][0], bf[2 * jp][1], bf[2 * jp + 1][0], bf[2 * jp + 1][1], addr);
        }
    };

    float acc[4][4][4];
#pragma unroll
    for (int i = 0; i < 4; i++)
#pragma unroll
        for (int j = 0; j < 4; j++)
#pragma unroll
            for (int r = 0; r < 4; r++) acc[i][j][r] = 0.f;

    auto mma16 = [&](uint32_t af[4][4], uint32_t bf[4][2]) {
#pragma unroll
        for (int j = 0; j < 4; j++)
#pragma unroll
            for (int i = 0; i < 4; i++)
                mma_f16(acc[i][j][0], acc[i][j][1], acc[i][j][2], acc[i][j][3],
                        af[i][0], af[i][1], af[i][2], af[i][3],
                        bf[j][0], bf[j][1]);
    };

    issue(0);
    issue(1);
    cp_wait<1>();
    __syncthreads();
    ldfrag(0, 0, af0, bf0);

    for (int kt = 0; kt < NK; kt++) {
        const int buf = kt % 3;
        ldfrag(buf, 1, af1, bf1);
        mma16(af0, bf0);
        const bool more2 = (kt + 2) < NK;
        if (more2) issue(kt + 2);
        ldfrag(buf, 2, af0, bf0);
        mma16(af1, bf1);
        ldfrag(buf, 3, af1, bf1);
        mma16(af0, bf0);
        mma16(af1, bf1);
        if (kt + 1 < NK) {
            if (more2) cp_wait<1>();
            else       cp_wait<0>();
            __syncthreads();
            ldfrag((kt + 1) % 3, 0, af0, bf0);
        }
    }

    // ---- epilogue: stage raw acc to smem, then gelu(a)*gate -> Mout ----
    __syncthreads();
    float* Cs = (float*)smc;
#pragma unroll
    for (int i = 0; i < 4; i++) {
        const int r0 = wm + i * 16 + g;
        const int r1 = r0 + 8;
#pragma unroll
        for (int j = 0; j < 4; j++) {
            const int col = wn + j * 8 + 2 * t;
            *(float2*)&Cs[r0 * CS_STR + col] = make_float2(acc[i][j][0], acc[i][j][1]);
            *(float2*)&Cs[r1 * CS_STR + col] = make_float2(acc[i][j][2], acc[i][j][3]);
        }
    }
    __syncthreads();

    const float is2 = 0.70710678118654752f;
    for (int i = tid; i < 128 * 32; i += 256) {
        const int r  = i >> 5;
        const int c2 = (i & 31) * 2;
        float a0 = Cs[r * CS_STR + c2    ] + bias[n0m + c2    ];
        float a1 = Cs[r * CS_STR + c2 + 1] + bias[n0m + c2 + 1];
        float g0 = Cs[r * CS_STR + 64 + c2    ] + bias[FF + n0m + c2    ];
        float g1 = Cs[r * CS_STR + 64 + c2 + 1] + bias[FF + n0m + c2 + 1];
        float o0 = 0.5f * a0 * (1.0f + erff(a0 * is2)) * g0;
        float o1 = 0.5f * a1 * (1.0f + erff(a1 * is2)) * g1;
        *(__half2*)&Mout[(size_t)(m0 + r) * FF + n0m + c2] =
            __floats2half2_rn(o0, o1);
    }
}

// ---------------------------------------------------------------------------
// RoPE -> fp16 attention operands (qkv fp16 in) — R11 version
// ---------------------------------------------------------------------------
__global__ void __launch_bounds__(256) rope_f16_kernel(
    const __half* __restrict__ qkv, const int* __restrict__ p,
    const float* __restrict__ freqs,
    __half* __restrict__ qh, __half* __restrict__ kh,
    __half* __restrict__ vth)
{
    const int idx4 = blockIdx.x * blockDim.x + threadIdx.x;
    const int per_row = D3 / 4;
    const int row = idx4 / per_row;
    const int c   = (idx4 - row * per_row) * 4;
    if (row >= NTOK) return;

    const __half* base = qkv + (size_t)row * D3 + c;
    float2 v01 = __half22float2(*(const __half2*)base);
    float2 v23 = __half22float2(*(const __half2*)(base + 2));

    if (c < 2 * DD) {
        const float pos = (float)p[row];
        const int dh = c & 63;
        const int off = (dh < 32) ? 32 : -32;
        float2 o01 = __half22float2(*(const __half2*)(base + off));
        float2 o23 = __half22float2(*(const __half2*)(base + off + 2));
        float vv[4] = {v01.x, v01.y, v23.x, v23.y};
        float oo[4] = {o01.x, o01.y, o23.x, o23.y};
        const bool isq = (c < DD);
        const float qs = isq ? 0.125f : 1.0f;
#pragma unroll
        for (int j = 0; j < 4; j++) {
            float a = pos * freqs[dh + j];
            float sn, cs;
            __sincosf(a, &sn, &cs);
            vv[j] = (vv[j] * cs + oo[j] * sn) * qs;
        }
        __half* dst = isq ? (qh + (size_t)row * DD + c)
                          : (kh + (size_t)row * DD + (c - DD));
        *(__half2*)(dst)     = __floats2half2_rn(vv[0], vv[1]);
        *(__half2*)(dst + 2) = __floats2half2_rn(vv[2], vv[3]);
    } else {
        const int cd = c - 2 * DD;
        const int h  = cd >> 6;
        const int d0 = cd & 63;
        const int b  = row / SS;
        const int s  = row - b * SS;
        __half* dst = vth + ((size_t)(b * HH + h) * DH) * SS + s;
        dst[(size_t)(d0 + 0) * SS] = __float2half_rn(v01.x);
        dst[(size_t)(d0 + 1) * SS] = __float2half_rn(v01.y);
        dst[(size_t)(d0 + 2) * SS] = __float2half_rn(v23.x);
        dst[(size_t)(d0 + 3) * SS] = __float2half_rn(v23.y);
    }
}

// ---------------------------------------------------------------------------
// Flash attention, fp16 mma, 32-key tiles (R11 version, proven)
// ---------------------------------------------------------------------------
#define FH_K    (64*72)
#define FH_KSZ  (32*72)
#define FH_VT   (FH_K + 2*FH_KSZ)
#define FH_VTSZ (64*40)
#define FH_TOT  (FH_VT + 2*FH_VTSZ)
#define FH_SMEM (FH_TOT * 2)

__global__ void __launch_bounds__(128) flash_attn_f16_kernel(
    const __half* __restrict__ qh, const __half* __restrict__ kh,
    const __half* __restrict__ vth, __half* __restrict__ O)
{
    extern __shared__ __align__(16) char smc[];
    __half* smh = (__half*)smc;
    const int tid  = threadIdx.x;
    const int warp = tid >> 5;
    const int lane = tid & 31;
    const int g = lane >> 2;
    const int t = lane & 3;
    const int wq = warp * 16;

    const int qt = blockIdx.x, h = blockIdx.y, b = blockIdx.z;
    const int rowBase = b * SS + qt * 64;
    const int cq = h * DH;
    const uint32_t smb = smem_u32(smh);
    const __half* vbh = vth + (size_t)(b * HH + h) * DH * SS;

    for (int i = tid; i < 64 * 8; i += 128) {
        int r = i >> 3, ch = (i & 7) * 8;
        *(uint4*)&smh[r * 72 + ch] =
            *(const uint4*)&qh[(size_t)(rowBase + r) * DD + cq + ch];
    }

    auto issue_tile = [&](int kt, int buf) {
        const __half* gK = kh + (size_t)(b * SS + kt * 32) * DD + cq;
        const uint32_t sK = smb + (FH_K + buf * FH_KSZ) * 2;
#pragma unroll
        for (int it = 0; it < 2; it++) {
            int i = tid + it * 128;
            int r = i >> 3, ch = (i & 7) * 8;
            cp_async16(sK + (r * 72 + ch) * 2, gK + (size_t)r * DD + ch);
        }
        const __half* gV = vbh + (size_t)kt * 32;
        const uint32_t sV = smb + (FH_VT + buf * FH_VTSZ) * 2;
#pragma unroll
        for (int it = 0; it < 2; it++) {
            int i = tid + it * 128;
            int r = i >> 2, ch = (i & 3) * 8;
            cp_async16(sV + (r * 40 + ch) * 2, gV + (size_t)r * SS + ch);
        }
        cp_commit();
    };
    issue_tile(0, 0);

    __syncthreads();

    uint32_t qf[4][4];
    {
        const uint32_t aRow = (uint32_t)(lane & 15);
        const uint32_t aKh  = (uint32_t)((lane >> 4) << 3);
#pragma unroll
        for (int ks = 0; ks < 4; ks++) {
            uint32_t addr = smb + (((uint32_t)wq + aRow) * 72 + ks * 16 + aKh) * 2;
            ldsm_x4(qf[ks][0], qf[ks][1], qf[ks][2], qf[ks][3], addr);
        }
    }

    uint32_t* Pw = (uint32_t*)(smh) + warp * (16 * 20);
    const uint32_t sPb = smb + (uint32_t)warp * 1280;

    const uint32_t aRow = (uint32_t)(lane & 15);
    const uint32_t aKh  = (uint32_t)((lane >> 4) << 3);
    const uint32_t bRow = (uint32_t)((lane & 7) + ((lane >> 4) << 3));
    const uint32_t bKh  = (uint32_t)(lane & 8);

    float m_i[2] = {-1e30f, -1e30f};
    float l_i[2] = {0.f, 0.f};
    float acc[8][4];
#pragma unroll
    for (int d = 0; d < 8; d++)
#pragma unroll
        for (int r = 0; r < 4; r++) acc[d][r] = 0.f;

    const int NT = SS / 32;
    for (int kt = 0; kt < NT; kt++) {
        const int cur = kt & 1;
        if (kt + 1 < NT) {
            issue_tile(kt + 1, 1 - cur);
            cp_wait<1>();
        } else {
            cp_wait<0>();
        }
        __syncthreads();

        const uint32_t sKb = smb + (FH_K  + cur * FH_KSZ)  * 2;
        const uint32_t sVb = smb + (FH_VT + cur * FH_VTSZ) * 2;

        float s4[4][4];
#pragma unroll
        for (int n = 0; n < 4; n++)
#pragma unroll
            for (int r = 0; r < 4; r++) s4[n][r] = 0.f;

#pragma unroll
        for (int ks = 0; ks < 4; ks++) {
            uint32_t kf[4][2];
#pragma unroll
            for (int jp = 0; jp < 2; jp++) {
                uint32_t addr = sKb + (((uint32_t)(jp * 16) + bRow) * 72 + ks * 16 + bKh) * 2;
                ldsm_x4(kf[2 * jp][0], kf[2 * jp][1],
                        kf[2 * jp + 1][0], kf[2 * jp + 1][1], addr);
            }
#pragma unroll
            for (int n = 0; n < 4; n++)
                mma_f16(s4[n][0], s4[n][1], s4[n][2], s4[n][3],
                        qf[ks][0], qf[ks][1], qf[ks][2], qf[ks][3],
                        kf[n][0], kf[n][1]);
        }

        float mx0 = -1e30f, mx1 = -1e30f;
#pragma unroll
        for (int n = 0; n < 4; n++) {
            mx0 = fmaxf(mx0, fmaxf(s4[n][0], s4[n][1]));
            mx1 = fmaxf(mx1, fmaxf(s4[n][2], s4[n][3]));
        }
        mx0 = fmaxf(mx0, __shfl_xor_sync(0xffffffffu, mx0, 1));
        mx0 = fmaxf(mx0, __shfl_xor_sync(0xffffffffu, mx0, 2));
        mx1 = fmaxf(mx1, __shfl_xor_sync(0xffffffffu, mx1, 1));
        mx1 = fmaxf(mx1, __shfl_xor_sync(0xffffffffu, mx1, 2));

        float mn0 = fmaxf(m_i[0], mx0);
        float mn1 = fmaxf(m_i[1], mx1);
        float cr0 = __expf(m_i[0] - mn0);
        float cr1 = __expf(m_i[1] - mn1);

        float sum0 = 0.f, sum1 = 0.f;
#pragma unroll
        for (int n = 0; n < 4; n++) {
            s4[n][0] = __expf(s4[n][0] - mn0);
            s4[n][1] = __expf(s4[n][1] - mn0);
            s4[n][2] = __expf(s4[n][2] - mn1);
            s4[n][3] = __expf(s4[n][3] - mn1);
            sum0 += s4[n][0] + s4[n][1];
            sum1 += s4[n][2] + s4[n][3];
        }
        sum0 += __shfl_xor_sync(0xffffffffu, sum0, 1);
        sum0 += __shfl_xor_sync(0xffffffffu, sum0, 2);
        sum1 += __shfl_xor_sync(0xffffffffu, sum1, 1);
        sum1 += __shfl_xor_sync(0xffffffffu, sum1, 2);

        l_i[0] = l_i[0] * cr0 + sum0;
        l_i[1] = l_i[1] * cr1 + sum1;
        m_i[0] = mn0; m_i[1] = mn1;

#pragma unroll
        for (int d = 0; d < 8; d++) {
            acc[d][0] *= cr0; acc[d][1] *= cr0;
            acc[d][2] *= cr1; acc[d][3] *= cr1;
        }

#pragma unroll
        for (int n = 0; n < 4; n++) {
            Pw[ g      * 20 + n * 4 + t] =
                h2_as_u32(__floats2half2_rn(s4[n][0], s4[n][1]));
            Pw[(g + 8) * 20 + n * 4 + t] =
                h2_as_u32(__floats2half2_rn(s4[n][2], s4[n][3]));
        }
        __syncwarp();

#pragma unroll
        for (int ks = 0; ks < 2; ks++) {
            uint32_t pa[4];
            {
                uint32_t addr = sPb + (aRow * 40 + ks * 16 + aKh) * 2;
                ldsm_x4(pa[0], pa[1], pa[2], pa[3], addr);
            }
            uint32_t vf[8][2];
#pragma unroll
            for (int dp = 0; dp < 4; dp++) {
                uint32_t addr = sVb + (((uint32_t)(dp * 16) + bRow) * 40 + ks * 16 + bKh) * 2;
                ldsm_x4(vf[2 * dp][0], vf[2 * dp][1],
                        vf[2 * dp + 1][0], vf[2 * dp + 1][1], addr);
            }
#pragma unroll
            for (int d = 0; d < 8; d++)
                mma_f16(acc[d][0], acc[d][1], acc[d][2], acc[d][3],
                        pa[0], pa[1], pa[2], pa[3], vf[d][0], vf[d][1]);
        }
        __syncthreads();
    }

    const float inv0 = 1.0f / l_i[0];
    const float inv1 = 1.0f / l_i[1];
    const int r0 = rowBase + wq + g;
    const int r1 = r0 + 8;
#pragma unroll
    for (int d = 0; d < 8; d++) {
        const int col = cq + d * 8 + 2 * t;
        *(__half2*)&O[(size_t)r0 * DD + col] =
            __floats2half2_rn(acc[d][0] * inv0, acc[d][1] * inv0);
        *(__half2*)&O[(size_t)r1 * DD + col] =
            __floats2half2_rn(acc[d][2] * inv1, acc[d][3] * inv1);
    }
}

// ---------------------------------------------------------------------------
// Fused residual add + LayerNorm (+ optional fp16 copy)
// ---------------------------------------------------------------------------
__global__ void __launch_bounds__(256) add_ln_kernel(
    const float* __restrict__ A, const float* __restrict__ R,
    const float* __restrict__ g, const float* __restrict__ be,
    float* __restrict__ out, __half* __restrict__ out_h)
{
    __shared__ float red[8];
    const int row = blockIdx.x, tid = threadIdx.x;
    const int lane = tid & 31, wid = tid >> 5;

    float4 a = ((const float4*)(A + (size_t)row * DD))[tid];
    float4 r = ((const float4*)(R + (size_t)row * DD))[tid];
    float4 t = make_float4(a.x + r.x, a.y + r.y, a.z + r.z, a.w + r.w);

    float ssum = t.x + t.y + t.z + t.w;
#pragma unroll
    for (int o = 16; o; o >>= 1) ssum += __shfl_xor_sync(0xffffffffu, ssum, o);
    if (lane == 0) red[wid] = ssum;
    __syncthreads();
    float mean = (red[0] + red[1] + red[2] + red[3] +
                  red[4] + red[5] + red[6] + red[7]) * (1.0f / DD);
    __syncthreads();

    float4 d = make_float4(t.x - mean, t.y - mean, t.z - mean, t.w - mean);
    float sq = d.x * d.x + d.y * d.y + d.z * d.z + d.w * d.w;
#pragma unroll
    for (int o = 16; o; o >>= 1) sq += __shfl_xor_sync(0xffffffffu, sq, o);
    if (lane == 0) red[wid] = sq;
    __syncthreads();
    float var = (red[0] + red[1] + red[2] + red[3] +
                 red[4] + red[5] + red[6] + red[7]) * (1.0f / DD);
    float rs = rsqrtf(var + 1e-5f);

    float4 gv = ((const float4*)g)[tid];
    float4 bv = ((const float4*)be)[tid];
    float4 o4 = make_float4(d.x * rs * gv.x + bv.x,
                            d.y * rs * gv.y + bv.y,
                            d.z * rs * gv.z + bv.z,
                            d.w * rs * gv.w + bv.w);
    ((float4*)(out + (size_t)row * DD))[tid] = o4;
    if (out_h) {
        __half2* oh = (__half2*)(out_h + (size_t)row * DD);
        oh[2 * tid]     = __floats2half2_rn(o4.x, o4.y);
        oh[2 * tid + 1] = __floats2half2_rn(o4.z, o4.w);
    }
}

// ---------------------------------------------------------------------------
// kernel_launch
// ---------------------------------------------------------------------------
extern "C" void kernel_launch(void* const* d_in, const int* in_sizes, int n_in,
                              void* d_out, int out_size)
{
    const float* x      = (const float*)d_in[0];
    const int*   p      = (const int*)  d_in[1];
    const float* Wqkv   = (const float*)d_in[2];
    const float* bqkv   = (const float*)d_in[3];
    const float* Wo     = (const float*)d_in[4];
    const float* bo     = (const float*)d_in[5];
    const float* gattn  = (const float*)d_in[6];
    const float* battn  = (const float*)d_in[7];
    const float* W1     = (const float*)d_in[8];
    const float* b1     = (const float*)d_in[9];
    const float* W2     = (const float*)d_in[10];
    const float* b2     = (const float*)d_in[11];
    const float* gmlp   = (const float*)d_in[12];
    const float* bmlp   = (const float*)d_in[13];
    const float* freqs  = (const float*)d_in[14];
    float* out = (float*)d_out;

    float *proj, *hbuf, *m2;
    __half *qkvh, *xh, *wqkvh, *woh, *w1h, *w2h, *attnh, *hh, *mh;
    __half *qh, *kh, *vth;
    cudaGetSymbolAddress((void**)&proj, g_proj);
    cudaGetSymbolAddress((void**)&hbuf, g_hbuf);
    cudaGetSymbolAddress((void**)&m2,   g_m2);
    cudaGetSymbolAddress((void**)&qkvh, g_qkvh);
    cudaGetSymbolAddress((void**)&xh,    g_xh);
    cudaGetSymbolAddress((void**)&wqkvh, g_wqkvh);
    cudaGetSymbolAddress((void**)&woh,   g_woh);
    cudaGetSymbolAddress((void**)&w1h,   g_w1h);
    cudaGetSymbolAddress((void**)&w2h,   g_w2h);
    cudaGetSymbolAddress((void**)&attnh, g_attnh);
    cudaGetSymbolAddress((void**)&hh,    g_hh);
    cudaGetSymbolAddress((void**)&mh,    g_mh);
    cudaGetSymbolAddress((void**)&qh,    g_qh);
    cudaGetSymbolAddress((void**)&kh,    g_kh);
    cudaGetSymbolAddress((void**)&vth,   g_vth);

    cudaFuncSetAttribute(flash_attn_f16_kernel,
                         cudaFuncAttributeMaxDynamicSharedMemorySize, FH_SMEM);
    cudaFuncSetAttribute(gemm_f16_nt_bias<float>,
                         cudaFuncAttributeMaxDynamicSharedMemorySize, GH_SMEM);
    cudaFuncSetAttribute(gemm_f16_nt_bias<__half>,
                         cudaFuncAttributeMaxDynamicSharedMemorySize, GH_SMEM);
    cudaFuncSetAttribute(gemm_w1_gelu,
                         cudaFuncAttributeMaxDynamicSharedMemorySize, W1_SMEM);

    // 0) fp16 pre-conversion of all GEMM inputs (single launch)
    h_copy_all<<<(CP_N4 + 255) / 256, 256>>>(
        x, Wqkv, Wo, W1, W2, xh, wqkvh, woh, w1h, w2h);

    // 1) QKV projection (fp16 TC, fp16 out)
    gemm_f16_nt_bias<__half><<<dim3(D3 / 128, NTOK / 128), 256, GH_SMEM>>>(
        xh, wqkvh, bqkv, qkvh, NTOK, D3, DD);

    // 2) RoPE -> fp16 q/k + transposed fp16 V
    rope_f16_kernel<<<(NTOK * D3 / 4) / 256, 256>>>(qkvh, p, freqs, qh, kh, vth);

    // 3) Flash attention (fp16 TC), fp16 output
    flash_attn_f16_kernel<<<dim3(SS / 64, HH, BB), 128, FH_SMEM>>>(
        qh, kh, vth, attnh);

    // 4) Output projection
    gemm_f16_nt_bias<float><<<dim3(DD / 128, NTOK / 128), 256, GH_SMEM>>>(
        attnh, woh, bo, proj, NTOK, DD, DD);

    // 5) h = LN(proj + x); fp16 copy for W1 GEMM
    add_ln_kernel<<<NTOK, 256>>>(proj, x, gattn, battn, hbuf, hh);

    // 6+7) m = gelu(h@W1a^T + b1a) * (h@W1g^T + b1g) — fused
    gemm_w1_gelu<<<dim3(FF / 64, NTOK / 128), 256, W1_SMEM>>>(
        hh, w1h, b1, mh, NTOK, DD);

    // 8) m2 = m @ W2^T + b2
    gemm_f16_nt_bias<float><<<dim3(DD / 128, NTOK / 128), 256, GH_SMEM>>>(
        mh, w2h, b2, m2, NTOK, DD, FF);

    // 9) out = LN(m2 + h)
    add_ln_kernel<<<NTOK, 256>>>(m2, hbuf, gmlp, bmlp, out, nullptr);
}

// round 14
// speedup vs baseline: 1.1054x; 1.1054x over previous
#include <cuda_runtime.h>
#include <cuda_fp16.h>
#include <math.h>
#include <stdint.h>
#include <string.h>

// Problem constants
#define BB   2
#define SS   2048
#define DD   1024
#define HH   16
#define DH   64
#define FF   4096
#define NTOK (BB*SS)          // 4096 rows
#define D3   (3*DD)           // 3072

// ---------------------------------------------------------------------------
// Scratch (static device globals)
// ---------------------------------------------------------------------------
__device__ float  g_proj[NTOK * DD];
__device__ float  g_hbuf[NTOK * DD];
__device__ float  g_m2  [NTOK * DD];
__device__ __half g_qkvh [NTOK * D3];
__device__ __half g_xh   [NTOK * DD];
__device__ __half g_wqkvh[D3 * DD];
__device__ __half g_woh  [DD * DD];
__device__ __half g_w1h  [2 * FF * DD];
__device__ __half g_w2h  [DD * FF];
__device__ __half g_attnh[NTOK * DD];
__device__ __half g_hh   [NTOK * DD];
__device__ __half g_mh   [NTOK * FF];
__device__ __half g_qh   [NTOK * DD];
__device__ __half g_kh   [NTOK * DD];
__device__ __half g_vth  [BB * HH * DH * SS];

// ---------------------------------------------------------------------------
// helpers
// ---------------------------------------------------------------------------
__device__ __forceinline__ uint32_t h2_as_u32(__half2 h) {
    uint32_t u; memcpy(&u, &h, 4); return u;
}

__device__ __forceinline__ void mma_f16(
    float& d0, float& d1, float& d2, float& d3,
    uint32_t a0, uint32_t a1, uint32_t a2, uint32_t a3,
    uint32_t b0, uint32_t b1)
{
    asm volatile(
        "mma.sync.aligned.m16n8k16.row.col.f32.f16.f16.f32 "
        "{%0,%1,%2,%3}, {%4,%5,%6,%7}, {%8,%9}, {%0,%1,%2,%3};"
        : "+f"(d0), "+f"(d1), "+f"(d2), "+f"(d3)
        : "r"(a0), "r"(a1), "r"(a2), "r"(a3), "r"(b0), "r"(b1));
}

__device__ __forceinline__ void ldsm_x4(
    uint32_t& r0, uint32_t& r1, uint32_t& r2, uint32_t& r3, uint32_t addr)
{
    asm volatile(
        "ldmatrix.sync.aligned.m8n8.x4.shared.b16 {%0,%1,%2,%3}, [%4];"
        : "=r"(r0), "=r"(r1), "=r"(r2), "=r"(r3) : "r"(addr));
}

__device__ __forceinline__ uint32_t smem_u32(const void* p) {
    uint32_t a;
    asm("{ .reg .u64 t; cvta.to.shared.u64 t, %1; cvt.u32.u64 %0, t; }"
        : "=r"(a) : "l"(p));
    return a;
}

__device__ __forceinline__ void cp_async16(uint32_t s, const void* g) {
    asm volatile("cp.async.cg.shared.global [%0], [%1], 16;\n"
                 :: "r"(s), "l"(g));
}
__device__ __forceinline__ void cp_commit() {
    asm volatile("cp.async.commit_group;\n");
}
template<int N> __device__ __forceinline__ void cp_wait() {
    asm volatile("cp.async.wait_group %0;\n" :: "n"(N));
}

__device__ __forceinline__ void store2(float* C, size_t idx, float a, float b) {
    *(float2*)&C[idx] = make_float2(a, b);
}
__device__ __forceinline__ void store2(__half* C, size_t idx, float a, float b) {
    *(__half2*)&C[idx] = __floats2half2_rn(a, b);
}

// ---------------------------------------------------------------------------
// Merged fp32 -> fp16 conversion for all five GEMM inputs (one launch)
// ---------------------------------------------------------------------------
#define CP_N0 (NTOK * DD / 4)
#define CP_N1 (CP_N0 + D3 * DD / 4)
#define CP_N2 (CP_N1 + DD * DD / 4)
#define CP_N3 (CP_N2 + 2 * FF * DD / 4)
#define CP_N4 (CP_N3 + DD * FF / 4)

__global__ void __launch_bounds__(256) h_copy_all(
    const float* __restrict__ x, const float* __restrict__ wqkv,
    const float* __restrict__ wo, const float* __restrict__ w1,
    const float* __restrict__ w2,
    __half* __restrict__ xh, __half* __restrict__ wqkvh,
    __half* __restrict__ woh, __half* __restrict__ w1h,
    __half* __restrict__ w2h)
{
    int i = blockIdx.x * blockDim.x + threadIdx.x;
    if (i >= CP_N4) return;
    const float* s; __half* d; int off;
    if      (i < CP_N0) { s = x;    d = xh;    off = i; }
    else if (i < CP_N1) { s = wqkv; d = wqkvh; off = i - CP_N0; }
    else if (i < CP_N2) { s = wo;   d = woh;   off = i - CP_N1; }
    else if (i < CP_N3) { s = w1;   d = w1h;   off = i - CP_N2; }
    else                { s = w2;   d = w2h;   off = i - CP_N3; }
    float4 v = ((const float4*)s)[off];
    ((__half2*)d)[2 * off]     = __floats2half2_rn(v.x, v.y);
    ((__half2*)d)[2 * off + 1] = __floats2half2_rn(v.z, v.w);
}

// ---------------------------------------------------------------------------
// GEMM tile parameters (R11): CTA 128x128, BK=32, 3-stage, 8 warps
// ---------------------------------------------------------------------------
#define HSTR    40
#define STAGE_H (2 * 128 * HSTR)
#define GH_SMEM (3 * STAGE_H * 2)          // 61440 B

// ---------------------------------------------------------------------------
// FP16 tensor-core GEMM: C = A @ W^T + bias
// ---------------------------------------------------------------------------
template<typename OutT>
__global__ void __launch_bounds__(256) gemm_f16_nt_bias(
    const __half* __restrict__ A, const __half* __restrict__ W,
    const float* __restrict__ bias, OutT* __restrict__ C,
    int M, int N, int K)
{
    extern __shared__ __align__(16) char smc[];
    __half* smh = (__half*)smc;

    const int tid  = threadIdx.x;
    const int m0   = blockIdx.y * 128;
    const int n0   = blockIdx.x * 128;
    const int warp = tid >> 5;
    const int lane = tid & 31;
    const int g    = lane >> 2;
    const int t    = lane & 3;
    const int wm   = (warp >> 2) * 64;
    const int wn   = (warp & 3) * 32;

    const int lrow = tid >> 1;
    const int lc   = (tid & 1) * 16;
    const __half* Ag = A + (size_t)(m0 + lrow) * K + lc;
    const __half* Wg = W + (size_t)(n0 + lrow) * K + lc;
    const uint32_t smb = smem_u32(smh);

    const int NK = K >> 5;

    auto issue = [&](int kt) {
        const int buf = kt % 3;
        uint32_t dA = smb + (uint32_t)(buf * STAGE_H + lrow * HSTR + lc) * 2;
        uint32_t dB = dA + 128 * HSTR * 2;
        const __half* a = Ag + (size_t)kt * 32;
        const __half* w = Wg + (size_t)kt * 32;
        cp_async16(dA,      a);
        cp_async16(dA + 16, a + 8);
        cp_async16(dB,      w);
        cp_async16(dB + 16, w + 8);
        cp_commit();
    };

    const uint32_t aRow = (uint32_t)(lane & 15);
    const uint32_t aKh  = (uint32_t)((lane >> 4) << 3);
    const uint32_t bRow = (uint32_t)((lane & 7) + ((lane >> 4) << 3));
    const uint32_t bKh  = (uint32_t)(lane & 8);

    uint32_t af0[4][4], bf0[4][2], af1[4][4], bf1[4][2];

    auto ldfrag = [&](int buf, int ks, uint32_t af[4][4], uint32_t bf[4][2]) {
        const uint32_t aBase = smb + (uint32_t)(buf * STAGE_H) * 2;
        const uint32_t bBase = aBase + 128 * HSTR * 2;
        const uint32_t kh = (uint32_t)(ks * 16);
#pragma unroll
        for (int i = 0; i < 4; i++) {
            uint32_t addr = aBase + (((uint32_t)(wm + i * 16) + aRow) * HSTR + kh + aKh) * 2;
            ldsm_x4(af[i][0], af[i][1], af[i][2], af[i][3], addr);
        }
#pragma unroll
        for (int jp = 0; jp < 2; jp++) {
            uint32_t addr = bBase + (((uint32_t)(wn + jp * 16) + bRow) * HSTR + kh + bKh) * 2;
            ldsm_x4(bf[2 * jp][0], bf[2 * jp][1], bf[2 * jp + 1][0], bf[2 * jp + 1][1], addr);
        }
    };

    float acc[4][4][4];
#pragma unroll
    for (int i = 0; i < 4; i++)
#pragma unroll
        for (int j = 0; j < 4; j++)
#pragma unroll
            for (int r = 0; r < 4; r++) acc[i][j][r] = 0.f;

    auto mma16 = [&](uint32_t af[4][4], uint32_t bf[4][2]) {
#pragma unroll
        for (int j = 0; j < 4; j++)
#pragma unroll
            for (int i = 0; i < 4; i++)
                mma_f16(acc[i][j][0], acc[i][j][1], acc[i][j][2], acc[i][j][3],
                        af[i][0], af[i][1], af[i][2], af[i][3],
                        bf[j][0], bf[j][1]);
    };

    issue(0);
    issue(1);
    cp_wait<1>();
    __syncthreads();
    ldfrag(0, 0, af0, bf0);

    for (int kt = 0; kt < NK; kt++) {
        const int buf = kt % 3;
        ldfrag(buf, 1, af1, bf1);
        mma16(af0, bf0);
        const bool more2 = (kt + 2) < NK;
        if (more2) issue(kt + 2);
        mma16(af1, bf1);
        if (kt + 1 < NK) {
            if (more2) cp_wait<1>();
            else       cp_wait<0>();
            __syncthreads();
            ldfrag((kt + 1) % 3, 0, af0, bf0);
        }
    }

#pragma unroll
    for (int i = 0; i < 4; i++) {
        const int r0 = m0 + wm + i * 16 + g;
        const int r1 = r0 + 8;
#pragma unroll
        for (int j = 0; j < 4; j++) {
            const int col = n0 + wn + j * 8 + 2 * t;
            float2 bv = *(const float2*)&bias[col];
            store2(C, (size_t)r0 * N + col, acc[i][j][0] + bv.x, acc[i][j][1] + bv.y);
            store2(C, (size_t)r1 * N + col, acc[i][j][2] + bv.x, acc[i][j][3] + bv.y);
        }
    }
}

// ---------------------------------------------------------------------------
// W1 GEMM fused with GELU*gate (R11 version)
// ---------------------------------------------------------------------------
#define CS_STR   132
#define W1_SMEM  (128 * CS_STR * 4)

__global__ void __launch_bounds__(256) gemm_w1_gelu(
    const __half* __restrict__ A, const __half* __restrict__ W,
    const float* __restrict__ bias, __half* __restrict__ Mout,
    int M, int K)
{
    extern __shared__ __align__(16) char smc[];
    __half* smh = (__half*)smc;

    const int tid  = threadIdx.x;
    const int m0   = blockIdx.y * 128;
    const int n0m  = blockIdx.x * 64;
    const int warp = tid >> 5;
    const int lane = tid & 31;
    const int g    = lane >> 2;
    const int t    = lane & 3;
    const int wm   = (warp >> 2) * 64;
    const int wn   = (warp & 3) * 32;

    const int lrow = tid >> 1;
    const int lc   = (tid & 1) * 16;
    const int wrow = (lrow < 64) ? (n0m + lrow) : (FF + n0m + lrow - 64);
    const __half* Ag = A + (size_t)(m0 + lrow) * K + lc;
    const __half* Wg = W + (size_t)wrow * K + lc;
    const uint32_t smb = smem_u32(smh);

    const int NK = K >> 5;

    auto issue = [&](int kt) {
        const int buf = kt % 3;
        uint32_t dA = smb + (uint32_t)(buf * STAGE_H + lrow * HSTR + lc) * 2;
        uint32_t dB = dA + 128 * HSTR * 2;
        const __half* a = Ag + (size_t)kt * 32;
        const __half* w = Wg + (size_t)kt * 32;
        cp_async16(dA,      a);
        cp_async16(dA + 16, a + 8);
        cp_async16(dB,      w);
        cp_async16(dB + 16, w + 8);
        cp_commit();
    };

    const uint32_t aRow = (uint32_t)(lane & 15);
    const uint32_t aKh  = (uint32_t)((lane >> 4) << 3);
    const uint32_t bRow = (uint32_t)((lane & 7) + ((lane >> 4) << 3));
    const uint32_t bKh  = (uint32_t)(lane & 8);

    uint32_t af0[4][4], bf0[4][2], af1[4][4], bf1[4][2];

    auto ldfrag = [&](int buf, int ks, uint32_t af[4][4], uint32_t bf[4][2]) {
        const uint32_t aBase = smb + (uint32_t)(buf * STAGE_H) * 2;
        const uint32_t bBase = aBase + 128 * HSTR * 2;
        const uint32_t kh = (uint32_t)(ks * 16);
#pragma unroll
        for (int i = 0; i < 4; i++) {
            uint32_t addr = aBase + (((uint32_t)(wm + i * 16) + aRow) * HSTR + kh + aKh) * 2;
            ldsm_x4(af[i][0], af[i][1], af[i][2], af[i][3], addr);
        }
#pragma unroll
        for (int jp = 0; jp < 2; jp++) {
            uint32_t addr = bBase + (((uint32_t)(wn + jp * 16) + bRow) * HSTR + kh + bKh) * 2;
            ldsm_x4(bf[2 * jp][0], bf[2 * jp][1], bf[2 * jp + 1][0], bf[2 * jp + 1][1], addr);
        }
    };

    float acc[4][4][4];
#pragma unroll
    for (int i = 0; i < 4; i++)
#pragma unroll
        for (int j = 0; j < 4; j++)
#pragma unroll
            for (int r = 0; r < 4; r++) acc[i][j][r] = 0.f;

    auto mma16 = [&](uint32_t af[4][4], uint32_t bf[4][2]) {
#pragma unroll
        for (int j = 0; j < 4; j++)
#pragma unroll
            for (int i = 0; i < 4; i++)
                mma_f16(acc[i][j][0], acc[i][j][1], acc[i][j][2], acc[i][j][3],
                        af[i][0], af[i][1], af[i][2], af[i][3],
                        bf[j][0], bf[j][1]);
    };

    issue(0);
    issue(1);
    cp_wait<1>();
    __syncthreads();
    ldfrag(0, 0, af0, bf0);

    for (int kt = 0; kt < NK; kt++) {
        const int buf = kt % 3;
        ldfrag(buf, 1, af1, bf1);
        mma16(af0, bf0);
        const bool more2 = (kt + 2) < NK;
        if (more2) issue(kt + 2);
        mma16(af1, bf1);
        if (kt + 1 < NK) {
            if (more2) cp_wait<1>();
            else       cp_wait<0>();
            __syncthreads();
            ldfrag((kt + 1) % 3, 0, af0, bf0);
        }
    }

    __syncthreads();
    float* Cs = (float*)smc;
#pragma unroll
    for (int i = 0; i < 4; i++) {
        const int r0 = wm + i * 16 + g;
        const int r1 = r0 + 8;
#pragma unroll
        for (int j = 0; j < 4; j++) {
            const int col = wn + j * 8 + 2 * t;
            *(float2*)&Cs[r0 * CS_STR + col] = make_float2(acc[i][j][0], acc[i][j][1]);
            *(float2*)&Cs[r1 * CS_STR + col] = make_float2(acc[i][j][2], acc[i][j][3]);
        }
    }
    __syncthreads();

    const float is2 = 0.70710678118654752f;
    for (int i = tid; i < 128 * 32; i += 256) {
        const int r  = i >> 5;
        const int c2 = (i & 31) * 2;
        float a0 = Cs[r * CS_STR + c2    ] + bias[n0m + c2    ];
        float a1 = Cs[r * CS_STR + c2 + 1] + bias[n0m + c2 + 1];
        float g0 = Cs[r * CS_STR + 64 + c2    ] + bias[FF + n0m + c2    ];
        float g1 = Cs[r * CS_STR + 64 + c2 + 1] + bias[FF + n0m + c2 + 1];
        float o0 = 0.5f * a0 * (1.0f + erff(a0 * is2)) * g0;
        float o1 = 0.5f * a1 * (1.0f + erff(a1 * is2)) * g1;
        *(__half2*)&Mout[(size_t)(m0 + r) * FF + n0m + c2] =
            __floats2half2_rn(o0, o1);
    }
}

// ---------------------------------------------------------------------------
// RoPE -> fp16 attention operands (qkv fp16 in) — R11 version
// ---------------------------------------------------------------------------
__global__ void __launch_bounds__(256) rope_f16_kernel(
    const __half* __restrict__ qkv, const int* __restrict__ p,
    const float* __restrict__ freqs,
    __half* __restrict__ qh, __half* __restrict__ kh,
    __half* __restrict__ vth)
{
    const int idx4 = blockIdx.x * blockDim.x + threadIdx.x;
    const int per_row = D3 / 4;
    const int row = idx4 / per_row;
    const int c   = (idx4 - row * per_row) * 4;
    if (row >= NTOK) return;

    const __half* base = qkv + (size_t)row * D3 + c;
    float2 v01 = __half22float2(*(const __half2*)base);
    float2 v23 = __half22float2(*(const __half2*)(base + 2));

    if (c < 2 * DD) {
        const float pos = (float)p[row];
        const int dh = c & 63;
        const int off = (dh < 32) ? 32 : -32;
        float2 o01 = __half22float2(*(const __half2*)(base + off));
        float2 o23 = __half22float2(*(const __half2*)(base + off + 2));
        float vv[4] = {v01.x, v01.y, v23.x, v23.y};
        float oo[4] = {o01.x, o01.y, o23.x, o23.y};
        const bool isq = (c < DD);
        const float qs = isq ? 0.125f : 1.0f;
#pragma unroll
        for (int j = 0; j < 4; j++) {
            float a = pos * freqs[dh + j];
            float sn, cs;
            __sincosf(a, &sn, &cs);
            vv[j] = (vv[j] * cs + oo[j] * sn) * qs;
        }
        __half* dst = isq ? (qh + (size_t)row * DD + c)
                          : (kh + (size_t)row * DD + (c - DD));
        *(__half2*)(dst)     = __floats2half2_rn(vv[0], vv[1]);
        *(__half2*)(dst + 2) = __floats2half2_rn(vv[2], vv[3]);
    } else {
        const int cd = c - 2 * DD;
        const int h  = cd >> 6;
        const int d0 = cd & 63;
        const int b  = row / SS;
        const int s  = row - b * SS;
        __half* dst = vth + ((size_t)(b * HH + h) * DH) * SS + s;
        dst[(size_t)(d0 + 0) * SS] = __float2half_rn(v01.x);
        dst[(size_t)(d0 + 1) * SS] = __float2half_rn(v01.y);
        dst[(size_t)(d0 + 2) * SS] = __float2half_rn(v23.x);
        dst[(size_t)(d0 + 3) * SS] = __float2half_rn(v23.y);
    }
}

// ---------------------------------------------------------------------------
// Flash attention, fp16 mma, 32-key tiles (R11), min 5 blocks/SM
// ---------------------------------------------------------------------------
#define FH_K    (64*72)
#define FH_KSZ  (32*72)
#define FH_VT   (FH_K + 2*FH_KSZ)
#define FH_VTSZ (64*40)
#define FH_TOT  (FH_VT + 2*FH_VTSZ)
#define FH_SMEM (FH_TOT * 2)

__global__ void __launch_bounds__(128, 5) flash_attn_f16_kernel(
    const __half* __restrict__ qh, const __half* __restrict__ kh,
    const __half* __restrict__ vth, __half* __restrict__ O)
{
    extern __shared__ __align__(16) char smc[];
    __half* smh = (__half*)smc;
    const int tid  = threadIdx.x;
    const int warp = tid >> 5;
    const int lane = tid & 31;
    const int g = lane >> 2;
    const int t = lane & 3;
    const int wq = warp * 16;

    const int qt = blockIdx.x, h = blockIdx.y, b = blockIdx.z;
    const int rowBase = b * SS + qt * 64;
    const int cq = h * DH;
    const uint32_t smb = smem_u32(smh);
    const __half* vbh = vth + (size_t)(b * HH + h) * DH * SS;

    for (int i = tid; i < 64 * 8; i += 128) {
        int r = i >> 3, ch = (i & 7) * 8;
        *(uint4*)&smh[r * 72 + ch] =
            *(const uint4*)&qh[(size_t)(rowBase + r) * DD + cq + ch];
    }

    auto issue_tile = [&](int kt, int buf) {
        const __half* gK = kh + (size_t)(b * SS + kt * 32) * DD + cq;
        const uint32_t sK = smb + (FH_K + buf * FH_KSZ) * 2;
#pragma unroll
        for (int it = 0; it < 2; it++) {
            int i = tid + it * 128;
            int r = i >> 3, ch = (i & 7) * 8;
            cp_async16(sK + (r * 72 + ch) * 2, gK + (size_t)r * DD + ch);
        }
        const __half* gV = vbh + (size_t)kt * 32;
        const uint32_t sV = smb + (FH_VT + buf * FH_VTSZ) * 2;
#pragma unroll
        for (int it = 0; it < 2; it++) {
            int i = tid + it * 128;
            int r = i >> 2, ch = (i & 3) * 8;
            cp_async16(sV + (r * 40 + ch) * 2, gV + (size_t)r * SS + ch);
        }
        cp_commit();
    };
    issue_tile(0, 0);

    __syncthreads();

    uint32_t qf[4][4];
    {
        const uint32_t aRow = (uint32_t)(lane & 15);
        const uint32_t aKh  = (uint32_t)((lane >> 4) << 3);
#pragma unroll
        for (int ks = 0; ks < 4; ks++) {
            uint32_t addr = smb + (((uint32_t)wq + aRow) * 72 + ks * 16 + aKh) * 2;
            ldsm_x4(qf[ks][0], qf[ks][1], qf[ks][2], qf[ks][3], addr);
        }
    }

    uint32_t* Pw = (uint32_t*)(smh) + warp * (16 * 20);
    const uint32_t sPb = smb + (uint32_t)warp * 1280;

    const uint32_t aRow = (uint32_t)(lane & 15);
    const uint32_t aKh  = (uint32_t)((lane >> 4) << 3);
    const uint32_t bRow = (uint32_t)((lane & 7) + ((lane >> 4) << 3));
    const uint32_t bKh  = (uint32_t)(lane & 8);

    float m_i[2] = {-1e30f, -1e30f};
    float l_i[2] = {0.f, 0.f};
    float acc[8][4];
#pragma unroll
    for (int d = 0; d < 8; d++)
#pragma unroll
        for (int r = 0; r < 4; r++) acc[d][r] = 0.f;

    const int NT = SS / 32;
    for (int kt = 0; kt < NT; kt++) {
        const int cur = kt & 1;
        if (kt + 1 < NT) {
            issue_tile(kt + 1, 1 - cur);
            cp_wait<1>();
        } else {
            cp_wait<0>();
        }
        __syncthreads();

        const uint32_t sKb = smb + (FH_K  + cur * FH_KSZ)  * 2;
        const uint32_t sVb = smb + (FH_VT + cur * FH_VTSZ) * 2;

        float s4[4][4];
#pragma unroll
        for (int n = 0; n < 4; n++)
#pragma unroll
            for (int r = 0; r < 4; r++) s4[n][r] = 0.f;

#pragma unroll
        for (int ks = 0; ks < 4; ks++) {
            uint32_t kf[4][2];
#pragma unroll
            for (int jp = 0; jp < 2; jp++) {
                uint32_t addr = sKb + (((uint32_t)(jp * 16) + bRow) * 72 + ks * 16 + bKh) * 2;
                ldsm_x4(kf[2 * jp][0], kf[2 * jp][1],
                        kf[2 * jp + 1][0], kf[2 * jp + 1][1], addr);
            }
#pragma unroll
            for (int n = 0; n < 4; n++)
                mma_f16(s4[n][0], s4[n][1], s4[n][2], s4[n][3],
                        qf[ks][0], qf[ks][1], qf[ks][2], qf[ks][3],
                        kf[n][0], kf[n][1]);
        }

        float mx0 = -1e30f, mx1 = -1e30f;
#pragma unroll
        for (int n = 0; n < 4; n++) {
            mx0 = fmaxf(mx0, fmaxf(s4[n][0], s4[n][1]));
            mx1 = fmaxf(mx1, fmaxf(s4[n][2], s4[n][3]));
        }
        mx0 = fmaxf(mx0, __shfl_xor_sync(0xffffffffu, mx0, 1));
        mx0 = fmaxf(mx0, __shfl_xor_sync(0xffffffffu, mx0, 2));
        mx1 = fmaxf(mx1, __shfl_xor_sync(0xffffffffu, mx1, 1));
        mx1 = fmaxf(mx1, __shfl_xor_sync(0xffffffffu, mx1, 2));

        float mn0 = fmaxf(m_i[0], mx0);
        float mn1 = fmaxf(m_i[1], mx1);
        float cr0 = __expf(m_i[0] - mn0);
        float cr1 = __expf(m_i[1] - mn1);

        float sum0 = 0.f, sum1 = 0.f;
#pragma unroll
        for (int n = 0; n < 4; n++) {
            s4[n][0] = __expf(s4[n][0] - mn0);
            s4[n][1] = __expf(s4[n][1] - mn0);
            s4[n][2] = __expf(s4[n][2] - mn1);
            s4[n][3] = __expf(s4[n][3] - mn1);
            sum0 += s4[n][0] + s4[n][1];
            sum1 += s4[n][2] + s4[n][3];
        }
        sum0 += __shfl_xor_sync(0xffffffffu, sum0, 1);
        sum0 += __shfl_xor_sync(0xffffffffu, sum0, 2);
        sum1 += __shfl_xor_sync(0xffffffffu, sum1, 1);
        sum1 += __shfl_xor_sync(0xffffffffu, sum1, 2);

        l_i[0] = l_i[0] * cr0 + sum0;
        l_i[1] = l_i[1] * cr1 + sum1;
        m_i[0] = mn0; m_i[1] = mn1;

#pragma unroll
        for (int d = 0; d < 8; d++) {
            acc[d][0] *= cr0; acc[d][1] *= cr0;
            acc[d][2] *= cr1; acc[d][3] *= cr1;
        }

#pragma unroll
        for (int n = 0; n < 4; n++) {
            Pw[ g      * 20 + n * 4 + t] =
                h2_as_u32(__floats2half2_rn(s4[n][0], s4[n][1]));
            Pw[(g + 8) * 20 + n * 4 + t] =
                h2_as_u32(__floats2half2_rn(s4[n][2], s4[n][3]));
        }
        __syncwarp();

#pragma unroll
        for (int ks = 0; ks < 2; ks++) {
            uint32_t pa[4];
            {
                uint32_t addr = sPb + (aRow * 40 + ks * 16 + aKh) * 2;
                ldsm_x4(pa[0], pa[1], pa[2], pa[3], addr);
            }
            uint32_t vf[8][2];
#pragma unroll
            for (int dp = 0; dp < 4; dp++) {
                uint32_t addr = sVb + (((uint32_t)(dp * 16) + bRow) * 40 + ks * 16 + bKh) * 2;
                ldsm_x4(vf[2 * dp][0], vf[2 * dp][1],
                        vf[2 * dp + 1][0], vf[2 * dp + 1][1], addr);
            }
#pragma unroll
            for (int d = 0; d < 8; d++)
                mma_f16(acc[d][0], acc[d][1], acc[d][2], acc[d][3],
                        pa[0], pa[1], pa[2], pa[3], vf[d][0], vf[d][1]);
        }
        __syncthreads();
    }

    const float inv0 = 1.0f / l_i[0];
    const float inv1 = 1.0f / l_i[1];
    const int r0 = rowBase + wq + g;
    const int r1 = r0 + 8;
#pragma unroll
    for (int d = 0; d < 8; d++) {
        const int col = cq + d * 8 + 2 * t;
        *(__half2*)&O[(size_t)r0 * DD + col] =
            __floats2half2_rn(acc[d][0] * inv0, acc[d][1] * inv0);
        *(__half2*)&O[(size_t)r1 * DD + col] =
            __floats2half2_rn(acc[d][2] * inv1, acc[d][3] * inv1);
    }
}

// ---------------------------------------------------------------------------
// Fused residual add + LayerNorm (+ optional fp16 copy)
// ---------------------------------------------------------------------------
__global__ void __launch_bounds__(256) add_ln_kernel(
    const float* __restrict__ A, const float* __restrict__ R,
    const float* __restrict__ g, const float* __restrict__ be,
    float* __restrict__ out, __half* __restrict__ out_h)
{
    __shared__ float red[8];
    const int row = blockIdx.x, tid = threadIdx.x;
    const int lane = tid & 31, wid = tid >> 5;

    float4 a = ((const float4*)(A + (size_t)row * DD))[tid];
    float4 r = ((const float4*)(R + (size_t)row * DD))[tid];
    float4 t = make_float4(a.x + r.x, a.y + r.y, a.z + r.z, a.w + r.w);

    float ssum = t.x + t.y + t.z + t.w;
#pragma unroll
    for (int o = 16; o; o >>= 1) ssum += __shfl_xor_sync(0xffffffffu, ssum, o);
    if (lane == 0) red[wid] = ssum;
    __syncthreads();
    float mean = (red[0] + red[1] + red[2] + red[3] +
                  red[4] + red[5] + red[6] + red[7]) * (1.0f / DD);
    __syncthreads();

    float4 d = make_float4(t.x - mean, t.y - mean, t.z - mean, t.w - mean);
    float sq = d.x * d.x + d.y * d.y + d.z * d.z + d.w * d.w;
#pragma unroll
    for (int o = 16; o; o >>= 1) sq += __shfl_xor_sync(0xffffffffu, sq, o);
    if (lane == 0) red[wid] = sq;
    __syncthreads();
    float var = (red[0] + red[1] + red[2] + red[3] +
                 red[4] + red[5] + red[6] + red[7]) * (1.0f / DD);
    float rs = rsqrtf(var + 1e-5f);

    float4 gv = ((const float4*)g)[tid];
    float4 bv = ((const float4*)be)[tid];
    float4 o4 = make_float4(d.x * rs * gv.x + bv.x,
                            d.y * rs * gv.y + bv.y,
                            d.z * rs * gv.z + bv.z,
                            d.w * rs * gv.w + bv.w);
    ((float4*)(out + (size_t)row * DD))[tid] = o4;
    if (out_h) {
        __half2* oh = (__half2*)(out_h + (size_t)row * DD);
        oh[2 * tid]     = __floats2half2_rn(o4.x, o4.y);
        oh[2 * tid + 1] = __floats2half2_rn(o4.z, o4.w);
    }
}

// ---------------------------------------------------------------------------
// kernel_launch
// ---------------------------------------------------------------------------
extern "C" void kernel_launch(void* const* d_in, const int* in_sizes, int n_in,
                              void* d_out, int out_size)
{
    const float* x      = (const float*)d_in[0];
    const int*   p      = (const int*)  d_in[1];
    const float* Wqkv   = (const float*)d_in[2];
    const float* bqkv   = (const float*)d_in[3];
    const float* Wo     = (const float*)d_in[4];
    const float* bo     = (const float*)d_in[5];
    const float* gattn  = (const float*)d_in[6];
    const float* battn  = (const float*)d_in[7];
    const float* W1     = (const float*)d_in[8];
    const float* b1     = (const float*)d_in[9];
    const float* W2     = (const float*)d_in[10];
    const float* b2     = (const float*)d_in[11];
    const float* gmlp   = (const float*)d_in[12];
    const float* bmlp   = (const float*)d_in[13];
    const float* freqs  = (const float*)d_in[14];
    float* out = (float*)d_out;

    float *proj, *hbuf, *m2;
    __half *qkvh, *xh, *wqkvh, *woh, *w1h, *w2h, *attnh, *hh, *mh;
    __half *qh, *kh, *vth;
    cudaGetSymbolAddress((void**)&proj, g_proj);
    cudaGetSymbolAddress((void**)&hbuf, g_hbuf);
    cudaGetSymbolAddress((void**)&m2,   g_m2);
    cudaGetSymbolAddress((void**)&qkvh, g_qkvh);
    cudaGetSymbolAddress((void**)&xh,    g_xh);
    cudaGetSymbolAddress((void**)&wqkvh, g_wqkvh);
    cudaGetSymbolAddress((void**)&woh,   g_woh);
    cudaGetSymbolAddress((void**)&w1h,   g_w1h);
    cudaGetSymbolAddress((void**)&w2h,   g_w2h);
    cudaGetSymbolAddress((void**)&attnh, g_attnh);
    cudaGetSymbolAddress((void**)&hh,    g_hh);
    cudaGetSymbolAddress((void**)&mh,    g_mh);
    cudaGetSymbolAddress((void**)&qh,    g_qh);
    cudaGetSymbolAddress((void**)&kh,    g_kh);
    cudaGetSymbolAddress((void**)&vth,   g_vth);

    cudaFuncSetAttribute(flash_attn_f16_kernel,
                         cudaFuncAttributeMaxDynamicSharedMemorySize, FH_SMEM);
    cudaFuncSetAttribute(gemm_f16_nt_bias<float>,
                         cudaFuncAttributeMaxDynamicSharedMemorySize, GH_SMEM);
    cudaFuncSetAttribute(gemm_f16_nt_bias<__half>,
                         cudaFuncAttributeMaxDynamicSharedMemorySize, GH_SMEM);
    cudaFuncSetAttribute(gemm_w1_gelu,
                         cudaFuncAttributeMaxDynamicSharedMemorySize, W1_SMEM);

    // 0) fp16 pre-conversion of all GEMM inputs (single launch)
    h_copy_all<<<(CP_N4 + 255) / 256, 256>>>(
        x, Wqkv, Wo, W1, W2, xh, wqkvh, woh, w1h, w2h);

    // 1) QKV projection (fp16 TC, fp16 out)
    gemm_f16_nt_bias<__half><<<dim3(D3 / 128, NTOK / 128), 256, GH_SMEM>>>(
        xh, wqkvh, bqkv, qkvh, NTOK, D3, DD);

    // 2) RoPE -> fp16 q/k + transposed fp16 V
    rope_f16_kernel<<<(NTOK * D3 / 4) / 256, 256>>>(qkvh, p, freqs, qh, kh, vth);

    // 3) Flash attention (fp16 TC), fp16 output
    flash_attn_f16_kernel<<<dim3(SS / 64, HH, BB), 128, FH_SMEM>>>(
        qh, kh, vth, attnh);

    // 4) Output projection
    gemm_f16_nt_bias<float><<<dim3(DD / 128, NTOK / 128), 256, GH_SMEM>>>(
        attnh, woh, bo, proj, NTOK, DD, DD);

    // 5) h = LN(proj + x); fp16 copy for W1 GEMM
    add_ln_kernel<<<NTOK, 256>>>(proj, x, gattn, battn, hbuf, hh);

    // 6+7) m = gelu(h@W1a^T + b1a) * (h@W1g^T + b1g) — fused
    gemm_w1_gelu<<<dim3(FF / 64, NTOK / 128), 256, W1_SMEM>>>(
        hh, w1h, b1, mh, NTOK, DD);

    // 8) m2 = m @ W2^T + b2
    gemm_f16_nt_bias<float><<<dim3(DD / 128, NTOK / 128), 256, GH_SMEM>>>(
        mh, w2h, b2, m2, NTOK, DD, FF);

    // 9) out = LN(m2 + h)
    add_ln_kernel<<<NTOK, 256>>>(m2, hbuf, gmlp, bmlp, out, nullptr);
}

// round 15
// speedup vs baseline: 1.1189x; 1.0122x over previous
#include <cuda_runtime.h>
#include <cuda_fp16.h>
#include <math.h>
#include <stdint.h>
#include <string.h>

// Problem constants
#define BB   2
#define SS   2048
#define DD   1024
#define HH   16
#define DH   64
#define FF   4096
#define NTOK (BB*SS)          // 4096 rows
#define D3   (3*DD)           // 3072

// ---------------------------------------------------------------------------
// Scratch (static device globals)
// ---------------------------------------------------------------------------
__device__ float  g_hbuf[NTOK * DD];
__device__ __half g_qkvh [NTOK * D3];
__device__ __half g_xh   [NTOK * DD];
__device__ __half g_wqkvh[D3 * DD];
__device__ __half g_woh  [DD * DD];
__device__ __half g_w1h  [2 * FF * DD];
__device__ __half g_w2h  [DD * FF];
__device__ __half g_attnh[NTOK * DD];
__device__ __half g_projh[NTOK * DD];
__device__ __half g_m2h  [NTOK * DD];
__device__ __half g_hh   [NTOK * DD];
__device__ __half g_mh   [NTOK * FF];
__device__ __half g_qh   [NTOK * DD];
__device__ __half g_kh   [NTOK * DD];
__device__ __half g_vth  [BB * HH * DH * SS];

// ---------------------------------------------------------------------------
// helpers
// ---------------------------------------------------------------------------
__device__ __forceinline__ uint32_t h2_as_u32(__half2 h) {
    uint32_t u; memcpy(&u, &h, 4); return u;
}

__device__ __forceinline__ void mma_f16(
    float& d0, float& d1, float& d2, float& d3,
    uint32_t a0, uint32_t a1, uint32_t a2, uint32_t a3,
    uint32_t b0, uint32_t b1)
{
    asm volatile(
        "mma.sync.aligned.m16n8k16.row.col.f32.f16.f16.f32 "
        "{%0,%1,%2,%3}, {%4,%5,%6,%7}, {%8,%9}, {%0,%1,%2,%3};"
        : "+f"(d0), "+f"(d1), "+f"(d2), "+f"(d3)
        : "r"(a0), "r"(a1), "r"(a2), "r"(a3), "r"(b0), "r"(b1));
}

__device__ __forceinline__ void ldsm_x4(
    uint32_t& r0, uint32_t& r1, uint32_t& r2, uint32_t& r3, uint32_t addr)
{
    asm volatile(
        "ldmatrix.sync.aligned.m8n8.x4.shared.b16 {%0,%1,%2,%3}, [%4];"
        : "=r"(r0), "=r"(r1), "=r"(r2), "=r"(r3) : "r"(addr));
}

__device__ __forceinline__ uint32_t smem_u32(const void* p) {
    uint32_t a;
    asm("{ .reg .u64 t; cvta.to.shared.u64 t, %1; cvt.u32.u64 %0, t; }"
        : "=r"(a) : "l"(p));
    return a;
}

__device__ __forceinline__ void cp_async16(uint32_t s, const void* g) {
    asm volatile("cp.async.cg.shared.global [%0], [%1], 16;\n"
                 :: "r"(s), "l"(g));
}
__device__ __forceinline__ void cp_commit() {
    asm volatile("cp.async.commit_group;\n");
}
template<int N> __device__ __forceinline__ void cp_wait() {
    asm volatile("cp.async.wait_group %0;\n" :: "n"(N));
}

__device__ __forceinline__ void store2(float* C, size_t idx, float a, float b) {
    *(float2*)&C[idx] = make_float2(a, b);
}
__device__ __forceinline__ void store2(__half* C, size_t idx, float a, float b) {
    *(__half2*)&C[idx] = __floats2half2_rn(a, b);
}

// row-wise float4 load from fp32 or fp16 source (tid = float4 index)
__device__ __forceinline__ float4 load4(const float* p, int tid) {
    return ((const float4*)p)[tid];
}
__device__ __forceinline__ float4 load4(const __half* p, int tid) {
    __half2 h0 = ((const __half2*)p)[2 * tid];
    __half2 h1 = ((const __half2*)p)[2 * tid + 1];
    float2 f0 = __half22float2(h0), f1 = __half22float2(h1);
    return make_float4(f0.x, f0.y, f1.x, f1.y);
}

// ---------------------------------------------------------------------------
// Merged fp32 -> fp16 conversion for all five GEMM inputs (one launch)
// ---------------------------------------------------------------------------
#define CP_N0 (NTOK * DD / 4)
#define CP_N1 (CP_N0 + D3 * DD / 4)
#define CP_N2 (CP_N1 + DD * DD / 4)
#define CP_N3 (CP_N2 + 2 * FF * DD / 4)
#define CP_N4 (CP_N3 + DD * FF / 4)

__global__ void __launch_bounds__(256) h_copy_all(
    const float* __restrict__ x, const float* __restrict__ wqkv,
    const float* __restrict__ wo, const float* __restrict__ w1,
    const float* __restrict__ w2,
    __half* __restrict__ xh, __half* __restrict__ wqkvh,
    __half* __restrict__ woh, __half* __restrict__ w1h,
    __half* __restrict__ w2h)
{
    int i = blockIdx.x * blockDim.x + threadIdx.x;
    if (i >= CP_N4) return;
    const float* s; __half* d; int off;
    if      (i < CP_N0) { s = x;    d = xh;    off = i; }
    else if (i < CP_N1) { s = wqkv; d = wqkvh; off = i - CP_N0; }
    else if (i < CP_N2) { s = wo;   d = woh;   off = i - CP_N1; }
    else if (i < CP_N3) { s = w1;   d = w1h;   off = i - CP_N2; }
    else                { s = w2;   d = w2h;   off = i - CP_N3; }
    float4 v = ((const float4*)s)[off];
    ((__half2*)d)[2 * off]     = __floats2half2_rn(v.x, v.y);
    ((__half2*)d)[2 * off + 1] = __floats2half2_rn(v.z, v.w);
}

// ---------------------------------------------------------------------------
// GEMM tile parameters (R11): CTA 128x128, BK=32, 3-stage, 8 warps
// ---------------------------------------------------------------------------
#define HSTR    40
#define STAGE_H (2 * 128 * HSTR)
#define GH_SMEM (3 * STAGE_H * 2)          // 61440 B

// ---------------------------------------------------------------------------
// FP16 tensor-core GEMM: C = A @ W^T + bias
// ---------------------------------------------------------------------------
template<typename OutT>
__global__ void __launch_bounds__(256) gemm_f16_nt_bias(
    const __half* __restrict__ A, const __half* __restrict__ W,
    const float* __restrict__ bias, OutT* __restrict__ C,
    int M, int N, int K)
{
    extern __shared__ __align__(16) char smc[];
    __half* smh = (__half*)smc;

    const int tid  = threadIdx.x;
    const int m0   = blockIdx.y * 128;
    const int n0   = blockIdx.x * 128;
    const int warp = tid >> 5;
    const int lane = tid & 31;
    const int g    = lane >> 2;
    const int t    = lane & 3;
    const int wm   = (warp >> 2) * 64;
    const int wn   = (warp & 3) * 32;

    const int lrow = tid >> 1;
    const int lc   = (tid & 1) * 16;
    const __half* Ag = A + (size_t)(m0 + lrow) * K + lc;
    const __half* Wg = W + (size_t)(n0 + lrow) * K + lc;
    const uint32_t smb = smem_u32(smh);

    const int NK = K >> 5;

    auto issue = [&](int kt) {
        const int buf = kt % 3;
        uint32_t dA = smb + (uint32_t)(buf * STAGE_H + lrow * HSTR + lc) * 2;
        uint32_t dB = dA + 128 * HSTR * 2;
        const __half* a = Ag + (size_t)kt * 32;
        const __half* w = Wg + (size_t)kt * 32;
        cp_async16(dA,      a);
        cp_async16(dA + 16, a + 8);
        cp_async16(dB,      w);
        cp_async16(dB + 16, w + 8);
        cp_commit();
    };

    const uint32_t aRow = (uint32_t)(lane & 15);
    const uint32_t aKh  = (uint32_t)((lane >> 4) << 3);
    const uint32_t bRow = (uint32_t)((lane & 7) + ((lane >> 4) << 3));
    const uint32_t bKh  = (uint32_t)(lane & 8);

    uint32_t af0[4][4], bf0[4][2], af1[4][4], bf1[4][2];

    auto ldfrag = [&](int buf, int ks, uint32_t af[4][4], uint32_t bf[4][2]) {
        const uint32_t aBase = smb + (uint32_t)(buf * STAGE_H) * 2;
        const uint32_t bBase = aBase + 128 * HSTR * 2;
        const uint32_t kh = (uint32_t)(ks * 16);
#pragma unroll
        for (int i = 0; i < 4; i++) {
            uint32_t addr = aBase + (((uint32_t)(wm + i * 16) + aRow) * HSTR + kh + aKh) * 2;
            ldsm_x4(af[i][0], af[i][1], af[i][2], af[i][3], addr);
        }
#pragma unroll
        for (int jp = 0; jp < 2; jp++) {
            uint32_t addr = bBase + (((uint32_t)(wn + jp * 16) + bRow) * HSTR + kh + bKh) * 2;
            ldsm_x4(bf[2 * jp][0], bf[2 * jp][1], bf[2 * jp + 1][0], bf[2 * jp + 1][1], addr);
        }
    };

    float acc[4][4][4];
#pragma unroll
    for (int i = 0; i < 4; i++)
#pragma unroll
        for (int j = 0; j < 4; j++)
#pragma unroll
            for (int r = 0; r < 4; r++) acc[i][j][r] = 0.f;

    auto mma16 = [&](uint32_t af[4][4], uint32_t bf[4][2]) {
#pragma unroll
        for (int j = 0; j < 4; j++)
#pragma unroll
            for (int i = 0; i < 4; i++)
                mma_f16(acc[i][j][0], acc[i][j][1], acc[i][j][2], acc[i][j][3],
                        af[i][0], af[i][1], af[i][2], af[i][3],
                        bf[j][0], bf[j][1]);
    };

    issue(0);
    issue(1);
    cp_wait<1>();
    __syncthreads();
    ldfrag(0, 0, af0, bf0);

    for (int kt = 0; kt < NK; kt++) {
        const int buf = kt % 3;
        ldfrag(buf, 1, af1, bf1);
        mma16(af0, bf0);
        const bool more2 = (kt + 2) < NK;
        if (more2) issue(kt + 2);
        mma16(af1, bf1);
        if (kt + 1 < NK) {
            if (more2) cp_wait<1>();
            else       cp_wait<0>();
            __syncthreads();
            ldfrag((kt + 1) % 3, 0, af0, bf0);
        }
    }

#pragma unroll
    for (int i = 0; i < 4; i++) {
        const int r0 = m0 + wm + i * 16 + g;
        const int r1 = r0 + 8;
#pragma unroll
        for (int j = 0; j < 4; j++) {
            const int col = n0 + wn + j * 8 + 2 * t;
            float2 bv = *(const float2*)&bias[col];
            store2(C, (size_t)r0 * N + col, acc[i][j][0] + bv.x, acc[i][j][1] + bv.y);
            store2(C, (size_t)r1 * N + col, acc[i][j][2] + bv.x, acc[i][j][3] + bv.y);
        }
    }
}

// ---------------------------------------------------------------------------
// W1 GEMM fused with GELU*gate (R11 version)
// ---------------------------------------------------------------------------
#define CS_STR   132
#define W1_SMEM  (128 * CS_STR * 4)

__global__ void __launch_bounds__(256) gemm_w1_gelu(
    const __half* __restrict__ A, const __half* __restrict__ W,
    const float* __restrict__ bias, __half* __restrict__ Mout,
    int M, int K)
{
    extern __shared__ __align__(16) char smc[];
    __half* smh = (__half*)smc;

    const int tid  = threadIdx.x;
    const int m0   = blockIdx.y * 128;
    const int n0m  = blockIdx.x * 64;
    const int warp = tid >> 5;
    const int lane = tid & 31;
    const int g    = lane >> 2;
    const int t    = lane & 3;
    const int wm   = (warp >> 2) * 64;
    const int wn   = (warp & 3) * 32;

    const int lrow = tid >> 1;
    const int lc   = (tid & 1) * 16;
    const int wrow = (lrow < 64) ? (n0m + lrow) : (FF + n0m + lrow - 64);
    const __half* Ag = A + (size_t)(m0 + lrow) * K + lc;
    const __half* Wg = W + (size_t)wrow * K + lc;
    const uint32_t smb = smem_u32(smh);

    const int NK = K >> 5;

    auto issue = [&](int kt) {
        const int buf = kt % 3;
        uint32_t dA = smb + (uint32_t)(buf * STAGE_H + lrow * HSTR + lc) * 2;
        uint32_t dB = dA + 128 * HSTR * 2;
        const __half* a = Ag + (size_t)kt * 32;
        const __half* w = Wg + (size_t)kt * 32;
        cp_async16(dA,      a);
        cp_async16(dA + 16, a + 8);
        cp_async16(dB,      w);
        cp_async16(dB + 16, w + 8);
        cp_commit();
    };

    const uint32_t aRow = (uint32_t)(lane & 15);
    const uint32_t aKh  = (uint32_t)((lane >> 4) << 3);
    const uint32_t bRow = (uint32_t)((lane & 7) + ((lane >> 4) << 3));
    const uint32_t bKh  = (uint32_t)(lane & 8);

    uint32_t af0[4][4], bf0[4][2], af1[4][4], bf1[4][2];

    auto ldfrag = [&](int buf, int ks, uint32_t af[4][4], uint32_t bf[4][2]) {
        const uint32_t aBase = smb + (uint32_t)(buf * STAGE_H) * 2;
        const uint32_t bBase = aBase + 128 * HSTR * 2;
        const uint32_t kh = (uint32_t)(ks * 16);
#pragma unroll
        for (int i = 0; i < 4; i++) {
            uint32_t addr = aBase + (((uint32_t)(wm + i * 16) + aRow) * HSTR + kh + aKh) * 2;
            ldsm_x4(af[i][0], af[i][1], af[i][2], af[i][3], addr);
        }
#pragma unroll
        for (int jp = 0; jp < 2; jp++) {
            uint32_t addr = bBase + (((uint32_t)(wn + jp * 16) + bRow) * HSTR + kh + bKh) * 2;
            ldsm_x4(bf[2 * jp][0], bf[2 * jp][1], bf[2 * jp + 1][0], bf[2 * jp + 1][1], addr);
        }
    };

    float acc[4][4][4];
#pragma unroll
    for (int i = 0; i < 4; i++)
#pragma unroll
        for (int j = 0; j < 4; j++)
#pragma unroll
            for (int r = 0; r < 4; r++) acc[i][j][r] = 0.f;

    auto mma16 = [&](uint32_t af[4][4], uint32_t bf[4][2]) {
#pragma unroll
        for (int j = 0; j < 4; j++)
#pragma unroll
            for (int i = 0; i < 4; i++)
                mma_f16(acc[i][j][0], acc[i][j][1], acc[i][j][2], acc[i][j][3],
                        af[i][0], af[i][1], af[i][2], af[i][3],
                        bf[j][0], bf[j][1]);
    };

    issue(0);
    issue(1);
    cp_wait<1>();
    __syncthreads();
    ldfrag(0, 0, af0, bf0);

    for (int kt = 0; kt < NK; kt++) {
        const int buf = kt % 3;
        ldfrag(buf, 1, af1, bf1);
        mma16(af0, bf0);
        const bool more2 = (kt + 2) < NK;
        if (more2) issue(kt + 2);
        mma16(af1, bf1);
        if (kt + 1 < NK) {
            if (more2) cp_wait<1>();
            else       cp_wait<0>();
            __syncthreads();
            ldfrag((kt + 1) % 3, 0, af0, bf0);
        }
    }

    __syncthreads();
    float* Cs = (float*)smc;
#pragma unroll
    for (int i = 0; i < 4; i++) {
        const int r0 = wm + i * 16 + g;
        const int r1 = r0 + 8;
#pragma unroll
        for (int j = 0; j < 4; j++) {
            const int col = wn + j * 8 + 2 * t;
            *(float2*)&Cs[r0 * CS_STR + col] = make_float2(acc[i][j][0], acc[i][j][1]);
            *(float2*)&Cs[r1 * CS_STR + col] = make_float2(acc[i][j][2], acc[i][j][3]);
        }
    }
    __syncthreads();

    const float is2 = 0.70710678118654752f;
    for (int i = tid; i < 128 * 32; i += 256) {
        const int r  = i >> 5;
        const int c2 = (i & 31) * 2;
        float a0 = Cs[r * CS_STR + c2    ] + bias[n0m + c2    ];
        float a1 = Cs[r * CS_STR + c2 + 1] + bias[n0m + c2 + 1];
        float g0 = Cs[r * CS_STR + 64 + c2    ] + bias[FF + n0m + c2    ];
        float g1 = Cs[r * CS_STR + 64 + c2 + 1] + bias[FF + n0m + c2 + 1];
        float o0 = 0.5f * a0 * (1.0f + erff(a0 * is2)) * g0;
        float o1 = 0.5f * a1 * (1.0f + erff(a1 * is2)) * g1;
        *(__half2*)&Mout[(size_t)(m0 + r) * FF + n0m + c2] =
            __floats2half2_rn(o0, o1);
    }
}

// ---------------------------------------------------------------------------
// RoPE -> fp16 attention operands (qkv fp16 in) — R11 version
// ---------------------------------------------------------------------------
__global__ void __launch_bounds__(256) rope_f16_kernel(
    const __half* __restrict__ qkv, const int* __restrict__ p,
    const float* __restrict__ freqs,
    __half* __restrict__ qh, __half* __restrict__ kh,
    __half* __restrict__ vth)
{
    const int idx4 = blockIdx.x * blockDim.x + threadIdx.x;
    const int per_row = D3 / 4;
    const int row = idx4 / per_row;
    const int c   = (idx4 - row * per_row) * 4;
    if (row >= NTOK) return;

    const __half* base = qkv + (size_t)row * D3 + c;
    float2 v01 = __half22float2(*(const __half2*)base);
    float2 v23 = __half22float2(*(const __half2*)(base + 2));

    if (c < 2 * DD) {
        const float pos = (float)p[row];
        const int dh = c & 63;
        const int off = (dh < 32) ? 32 : -32;
        float2 o01 = __half22float2(*(const __half2*)(base + off));
        float2 o23 = __half22float2(*(const __half2*)(base + off + 2));
        float vv[4] = {v01.x, v01.y, v23.x, v23.y};
        float oo[4] = {o01.x, o01.y, o23.x, o23.y};
        const bool isq = (c < DD);
        const float qs = isq ? 0.125f : 1.0f;
#pragma unroll
        for (int j = 0; j < 4; j++) {
            float a = pos * freqs[dh + j];
            float sn, cs;
            __sincosf(a, &sn, &cs);
            vv[j] = (vv[j] * cs + oo[j] * sn) * qs;
        }
        __half* dst = isq ? (qh + (size_t)row * DD + c)
                          : (kh + (size_t)row * DD + (c - DD));
        *(__half2*)(dst)     = __floats2half2_rn(vv[0], vv[1]);
        *(__half2*)(dst + 2) = __floats2half2_rn(vv[2], vv[3]);
    } else {
        const int cd = c - 2 * DD;
        const int h  = cd >> 6;
        const int d0 = cd & 63;
        const int b  = row / SS;
        const int s  = row - b * SS;
        __half* dst = vth + ((size_t)(b * HH + h) * DH) * SS + s;
        dst[(size_t)(d0 + 0) * SS] = __float2half_rn(v01.x);
        dst[(size_t)(d0 + 1) * SS] = __float2half_rn(v01.y);
        dst[(size_t)(d0 + 2) * SS] = __float2half_rn(v23.x);
        dst[(size_t)(d0 + 3) * SS] = __float2half_rn(v23.y);
    }
}

// ---------------------------------------------------------------------------
// Flash attention, fp16 mma, 32-key tiles (exact R11 version)
// ---------------------------------------------------------------------------
#define FH_K    (64*72)
#define FH_KSZ  (32*72)
#define FH_VT   (FH_K + 2*FH_KSZ)
#define FH_VTSZ (64*40)
#define FH_TOT  (FH_VT + 2*FH_VTSZ)
#define FH_SMEM (FH_TOT * 2)

__global__ void __launch_bounds__(128) flash_attn_f16_kernel(
    const __half* __restrict__ qh, const __half* __restrict__ kh,
    const __half* __restrict__ vth, __half* __restrict__ O)
{
    extern __shared__ __align__(16) char smc[];
    __half* smh = (__half*)smc;
    const int tid  = threadIdx.x;
    const int warp = tid >> 5;
    const int lane = tid & 31;
    const int g = lane >> 2;
    const int t = lane & 3;
    const int wq = warp * 16;

    const int qt = blockIdx.x, h = blockIdx.y, b = blockIdx.z;
    const int rowBase = b * SS + qt * 64;
    const int cq = h * DH;
    const uint32_t smb = smem_u32(smh);
    const __half* vbh = vth + (size_t)(b * HH + h) * DH * SS;

    for (int i = tid; i < 64 * 8; i += 128) {
        int r = i >> 3, ch = (i & 7) * 8;
        *(uint4*)&smh[r * 72 + ch] =
            *(const uint4*)&qh[(size_t)(rowBase + r) * DD + cq + ch];
    }

    auto issue_tile = [&](int kt, int buf) {
        const __half* gK = kh + (size_t)(b * SS + kt * 32) * DD + cq;
        const uint32_t sK = smb + (FH_K + buf * FH_KSZ) * 2;
#pragma unroll
        for (int it = 0; it < 2; it++) {
            int i = tid + it * 128;
            int r = i >> 3, ch = (i & 7) * 8;
            cp_async16(sK + (r * 72 + ch) * 2, gK + (size_t)r * DD + ch);
        }
        const __half* gV = vbh + (size_t)kt * 32;
        const uint32_t sV = smb + (FH_VT + buf * FH_VTSZ) * 2;
#pragma unroll
        for (int it = 0; it < 2; it++) {
            int i = tid + it * 128;
            int r = i >> 2, ch = (i & 3) * 8;
            cp_async16(sV + (r * 40 + ch) * 2, gV + (size_t)r * SS + ch);
        }
        cp_commit();
    };
    issue_tile(0, 0);

    __syncthreads();

    uint32_t qf[4][4];
    {
        const uint32_t aRow = (uint32_t)(lane & 15);
        const uint32_t aKh  = (uint32_t)((lane >> 4) << 3);
#pragma unroll
        for (int ks = 0; ks < 4; ks++) {
            uint32_t addr = smb + (((uint32_t)wq + aRow) * 72 + ks * 16 + aKh) * 2;
            ldsm_x4(qf[ks][0], qf[ks][1], qf[ks][2], qf[ks][3], addr);
        }
    }

    uint32_t* Pw = (uint32_t*)(smh) + warp * (16 * 20);
    const uint32_t sPb = smb + (uint32_t)warp * 1280;

    const uint32_t aRow = (uint32_t)(lane & 15);
    const uint32_t aKh  = (uint32_t)((lane >> 4) << 3);
    const uint32_t bRow = (uint32_t)((lane & 7) + ((lane >> 4) << 3));
    const uint32_t bKh  = (uint32_t)(lane & 8);

    float m_i[2] = {-1e30f, -1e30f};
    float l_i[2] = {0.f, 0.f};
    float acc[8][4];
#pragma unroll
    for (int d = 0; d < 8; d++)
#pragma unroll
        for (int r = 0; r < 4; r++) acc[d][r] = 0.f;

    const int NT = SS / 32;
    for (int kt = 0; kt < NT; kt++) {
        const int cur = kt & 1;
        if (kt + 1 < NT) {
            issue_tile(kt + 1, 1 - cur);
            cp_wait<1>();
        } else {
            cp_wait<0>();
        }
        __syncthreads();

        const uint32_t sKb = smb + (FH_K  + cur * FH_KSZ)  * 2;
        const uint32_t sVb = smb + (FH_VT + cur * FH_VTSZ) * 2;

        float s4[4][4];
#pragma unroll
        for (int n = 0; n < 4; n++)
#pragma unroll
            for (int r = 0; r < 4; r++) s4[n][r] = 0.f;

#pragma unroll
        for (int ks = 0; ks < 4; ks++) {
            uint32_t kf[4][2];
#pragma unroll
            for (int jp = 0; jp < 2; jp++) {
                uint32_t addr = sKb + (((uint32_t)(jp * 16) + bRow) * 72 + ks * 16 + bKh) * 2;
                ldsm_x4(kf[2 * jp][0], kf[2 * jp][1],
                        kf[2 * jp + 1][0], kf[2 * jp + 1][1], addr);
            }
#pragma unroll
            for (int n = 0; n < 4; n++)
                mma_f16(s4[n][0], s4[n][1], s4[n][2], s4[n][3],
                        qf[ks][0], qf[ks][1], qf[ks][2], qf[ks][3],
                        kf[n][0], kf[n][1]);
        }

        float mx0 = -1e30f, mx1 = -1e30f;
#pragma unroll
        for (int n = 0; n < 4; n++) {
            mx0 = fmaxf(mx0, fmaxf(s4[n][0], s4[n][1]));
            mx1 = fmaxf(mx1, fmaxf(s4[n][2], s4[n][3]));
        }
        mx0 = fmaxf(mx0, __shfl_xor_sync(0xffffffffu, mx0, 1));
        mx0 = fmaxf(mx0, __shfl_xor_sync(0xffffffffu, mx0, 2));
        mx1 = fmaxf(mx1, __shfl_xor_sync(0xffffffffu, mx1, 1));
        mx1 = fmaxf(mx1, __shfl_xor_sync(0xffffffffu, mx1, 2));

        float mn0 = fmaxf(m_i[0], mx0);
        float mn1 = fmaxf(m_i[1], mx1);
        float cr0 = __expf(m_i[0] - mn0);
        float cr1 = __expf(m_i[1] - mn1);

        float sum0 = 0.f, sum1 = 0.f;
#pragma unroll
        for (int n = 0; n < 4; n++) {
            s4[n][0] = __expf(s4[n][0] - mn0);
            s4[n][1] = __expf(s4[n][1] - mn0);
            s4[n][2] = __expf(s4[n][2] - mn1);
            s4[n][3] = __expf(s4[n][3] - mn1);
            sum0 += s4[n][0] + s4[n][1];
            sum1 += s4[n][2] + s4[n][3];
        }
        sum0 += __shfl_xor_sync(0xffffffffu, sum0, 1);
        sum0 += __shfl_xor_sync(0xffffffffu, sum0, 2);
        sum1 += __shfl_xor_sync(0xffffffffu, sum1, 1);
        sum1 += __shfl_xor_sync(0xffffffffu, sum1, 2);

        l_i[0] = l_i[0] * cr0 + sum0;
        l_i[1] = l_i[1] * cr1 + sum1;
        m_i[0] = mn0; m_i[1] = mn1;

#pragma unroll
        for (int d = 0; d < 8; d++) {
            acc[d][0] *= cr0; acc[d][1] *= cr0;
            acc[d][2] *= cr1; acc[d][3] *= cr1;
        }

#pragma unroll
        for (int n = 0; n < 4; n++) {
            Pw[ g      * 20 + n * 4 + t] =
                h2_as_u32(__floats2half2_rn(s4[n][0], s4[n][1]));
            Pw[(g + 8) * 20 + n * 4 + t] =
                h2_as_u32(__floats2half2_rn(s4[n][2], s4[n][3]));
        }
        __syncwarp();

#pragma unroll
        for (int ks = 0; ks < 2; ks++) {
            uint32_t pa[4];
            {
                uint32_t addr = sPb + (aRow * 40 + ks * 16 + aKh) * 2;
                ldsm_x4(pa[0], pa[1], pa[2], pa[3], addr);
            }
            uint32_t vf[8][2];
#pragma unroll
            for (int dp = 0; dp < 4; dp++) {
                uint32_t addr = sVb + (((uint32_t)(dp * 16) + bRow) * 40 + ks * 16 + bKh) * 2;
                ldsm_x4(vf[2 * dp][0], vf[2 * dp][1],
                        vf[2 * dp + 1][0], vf[2 * dp + 1][1], addr);
            }
#pragma unroll
            for (int d = 0; d < 8; d++)
                mma_f16(acc[d][0], acc[d][1], acc[d][2], acc[d][3],
                        pa[0], pa[1], pa[2], pa[3], vf[d][0], vf[d][1]);
        }
        __syncthreads();
    }

    const float inv0 = 1.0f / l_i[0];
    const float inv1 = 1.0f / l_i[1];
    const int r0 = rowBase + wq + g;
    const int r1 = r0 + 8;
#pragma unroll
    for (int d = 0; d < 8; d++) {
        const int col = cq + d * 8 + 2 * t;
        *(__half2*)&O[(size_t)r0 * DD + col] =
            __floats2half2_rn(acc[d][0] * inv0, acc[d][1] * inv0);
        *(__half2*)&O[(size_t)r1 * DD + col] =
            __floats2half2_rn(acc[d][2] * inv1, acc[d][3] * inv1);
    }
}

// ---------------------------------------------------------------------------
// Fused residual add + LayerNorm; A may be fp32 or fp16.
// ---------------------------------------------------------------------------
template<typename AT>
__global__ void __launch_bounds__(256) add_ln_kernel(
    const AT* __restrict__ A, const float* __restrict__ R,
    const float* __restrict__ g, const float* __restrict__ be,
    float* __restrict__ out, __half* __restrict__ out_h)
{
    __shared__ float red[8];
    const int row = blockIdx.x, tid = threadIdx.x;
    const int lane = tid & 31, wid = tid >> 5;

    float4 a = load4(A + (size_t)row * DD, tid);
    float4 r = ((const float4*)(R + (size_t)row * DD))[tid];
    float4 t = make_float4(a.x + r.x, a.y + r.y, a.z + r.z, a.w + r.w);

    float ssum = t.x + t.y + t.z + t.w;
#pragma unroll
    for (int o = 16; o; o >>= 1) ssum += __shfl_xor_sync(0xffffffffu, ssum, o);
    if (lane == 0) red[wid] = ssum;
    __syncthreads();
    float mean = (red[0] + red[1] + red[2] + red[3] +
                  red[4] + red[5] + red[6] + red[7]) * (1.0f / DD);
    __syncthreads();

    float4 d = make_float4(t.x - mean, t.y - mean, t.z - mean, t.w - mean);
    float sq = d.x * d.x + d.y * d.y + d.z * d.z + d.w * d.w;
#pragma unroll
    for (int o = 16; o; o >>= 1) sq += __shfl_xor_sync(0xffffffffu, sq, o);
    if (lane == 0) red[wid] = sq;
    __syncthreads();
    float var = (red[0] + red[1] + red[2] + red[3] +
                 red[4] + red[5] + red[6] + red[7]) * (1.0f / DD);
    float rs = rsqrtf(var + 1e-5f);

    float4 gv = ((const float4*)g)[tid];
    float4 bv = ((const float4*)be)[tid];
    float4 o4 = make_float4(d.x * rs * gv.x + bv.x,
                            d.y * rs * gv.y + bv.y,
                            d.z * rs * gv.z + bv.z,
                            d.w * rs * gv.w + bv.w);
    ((float4*)(out + (size_t)row * DD))[tid] = o4;
    if (out_h) {
        __half2* oh = (__half2*)(out_h + (size_t)row * DD);
        oh[2 * tid]     = __floats2half2_rn(o4.x, o4.y);
        oh[2 * tid + 1] = __floats2half2_rn(o4.z, o4.w);
    }
}

// ---------------------------------------------------------------------------
// kernel_launch
// ---------------------------------------------------------------------------
extern "C" void kernel_launch(void* const* d_in, const int* in_sizes, int n_in,
                              void* d_out, int out_size)
{
    const float* x      = (const float*)d_in[0];
    const int*   p      = (const int*)  d_in[1];
    const float* Wqkv   = (const float*)d_in[2];
    const float* bqkv   = (const float*)d_in[3];
    const float* Wo     = (const float*)d_in[4];
    const float* bo     = (const float*)d_in[5];
    const float* gattn  = (const float*)d_in[6];
    const float* battn  = (const float*)d_in[7];
    const float* W1     = (const float*)d_in[8];
    const float* b1     = (const float*)d_in[9];
    const float* W2     = (const float*)d_in[10];
    const float* b2     = (const float*)d_in[11];
    const float* gmlp   = (const float*)d_in[12];
    const float* bmlp   = (const float*)d_in[13];
    const float* freqs  = (const float*)d_in[14];
    float* out = (float*)d_out;

    float *hbuf;
    __half *qkvh, *xh, *wqkvh, *woh, *w1h, *w2h, *attnh, *projh, *m2h, *hh, *mh;
    __half *qh, *kh, *vth;
    cudaGetSymbolAddress((void**)&hbuf, g_hbuf);
    cudaGetSymbolAddress((void**)&qkvh, g_qkvh);
    cudaGetSymbolAddress((void**)&xh,    g_xh);
    cudaGetSymbolAddress((void**)&wqkvh, g_wqkvh);
    cudaGetSymbolAddress((void**)&woh,   g_woh);
    cudaGetSymbolAddress((void**)&w1h,   g_w1h);
    cudaGetSymbolAddress((void**)&w2h,   g_w2h);
    cudaGetSymbolAddress((void**)&attnh, g_attnh);
    cudaGetSymbolAddress((void**)&projh, g_projh);
    cudaGetSymbolAddress((void**)&m2h,   g_m2h);
    cudaGetSymbolAddress((void**)&hh,    g_hh);
    cudaGetSymbolAddress((void**)&mh,    g_mh);
    cudaGetSymbolAddress((void**)&qh,    g_qh);
    cudaGetSymbolAddress((void**)&kh,    g_kh);
    cudaGetSymbolAddress((void**)&vth,   g_vth);

    cudaFuncSetAttribute(flash_attn_f16_kernel,
                         cudaFuncAttributeMaxDynamicSharedMemorySize, FH_SMEM);
    cudaFuncSetAttribute(gemm_f16_nt_bias<float>,
                         cudaFuncAttributeMaxDynamicSharedMemorySize, GH_SMEM);
    cudaFuncSetAttribute(gemm_f16_nt_bias<__half>,
                         cudaFuncAttributeMaxDynamicSharedMemorySize, GH_SMEM);
    cudaFuncSetAttribute(gemm_w1_gelu,
                         cudaFuncAttributeMaxDynamicSharedMemorySize, W1_SMEM);

    // 0) fp16 pre-conversion of all GEMM inputs (single launch)
    h_copy_all<<<(CP_N4 + 255) / 256, 256>>>(
        x, Wqkv, Wo, W1, W2, xh, wqkvh, woh, w1h, w2h);

    // 1) QKV projection (fp16 TC, fp16 out)
    gemm_f16_nt_bias<__half><<<dim3(D3 / 128, NTOK / 128), 256, GH_SMEM>>>(
        xh, wqkvh, bqkv, qkvh, NTOK, D3, DD);

    // 2) RoPE -> fp16 q/k + transposed fp16 V
    rope_f16_kernel<<<(NTOK * D3 / 4) / 256, 256>>>(qkvh, p, freqs, qh, kh, vth);

    // 3) Flash attention (fp16 TC), fp16 output
    flash_attn_f16_kernel<<<dim3(SS / 64, HH, BB), 128, FH_SMEM>>>(
        qh, kh, vth, attnh);

    // 4) Output projection (fp16 out)
    gemm_f16_nt_bias<__half><<<dim3(DD / 128, NTOK / 128), 256, GH_SMEM>>>(
        attnh, woh, bo, projh, NTOK, DD, DD);

    // 5) h = LN(projh + x); fp16 copy for W1 GEMM
    add_ln_kernel<__half><<<NTOK, 256>>>(projh, x, gattn, battn, hbuf, hh);

    // 6+7) m = gelu(h@W1a^T + b1a) * (h@W1g^T + b1g) — fused
    gemm_w1_gelu<<<dim3(FF / 64, NTOK / 128), 256, W1_SMEM>>>(
        hh, w1h, b1, mh, NTOK, DD);

    // 8) m2 = m @ W2^T + b2 (fp16 out)
    gemm_f16_nt_bias<__half><<<dim3(DD / 128, NTOK / 128), 256, GH_SMEM>>>(
        mh, w2h, b2, m2h, NTOK, DD, FF);

    // 9) out = LN(m2h + h)
    add_ln_kernel<__half><<<NTOK, 256>>>(m2h, hbuf, gmlp, bmlp, out, nullptr);
}